// round 12
// baseline (speedup 1.0000x reference)
#include <cuda_runtime.h>
#include <cuda_fp16.h>
#include <cstdint>

#define TT 512
#define NB 128
#define NSAMP 32768
#define KP0 224
#define KP1 416
#define AP 40    // GEMM smem stride (elems) for 32-wide k chunks
#define KR 208   // recurrence padded K (13 x k16)
#define KG 832   // gather-MLP padded K (2 x 416)
#define RCN2 32  // recurrence CTAs: 2 dirs x 16 batch slices (8 cols each)

// ---------------- static scratch (no allocation; zero-initialized at load) -------
__device__ float g_pre_f[(size_t)TT * 800 * NB];   // (t, gate, b)
__device__ float g_pre_b[(size_t)TT * 800 * NB];
__device__ float g_hid[(size_t)NSAMP * 200];       // MLP hidden (s, n)

// fp16 single-precision operand buffers (error model calibrated round 10)
__device__ __align__(16) __half g_w0[(size_t)2 * 896 * KP0];  // [dir][m][k]
__device__ __align__(16) __half g_w1[(size_t)2 * 896 * KP1];
__device__ __align__(16) __half g_x[(size_t)TT * NB * KP0];   // (t, b, k)
__device__ __align__(16) __half g_h0[(size_t)TT * NB * KP1];  // layer0 out (t,b,k)
// layer1 out, (b, t, u) padded to 416; pad region [400,416) stays zero forever
__device__ __align__(16) __half g_hbt[(size_t)NB * TT * 416];
// w1 padded: [256 rows][KG]
__device__ __align__(16) __half g_w1p[(size_t)256 * KG];
// recurrence weights, interleaved rows (u*4+g), [layer][dir][800][KR]
__device__ __align__(16) __half g_wr[(size_t)2 * 2 * 800 * KR];

// ---------------- helpers ----------------
__device__ __forceinline__ float sigf(float x) { return 1.f / (1.f + __expf(-x)); }
__device__ __forceinline__ float tanhfast(float x) {
    float e = __expf(-2.f * x);
    return (1.f - e) * (1.f / (1.f + e));
}
__device__ __forceinline__ uint32_t smem_u32(const void* p) {
    uint32_t a;
    asm("{ .reg .u64 t; cvta.to.shared.u64 t, %1; cvt.u32.u64 %0, t; }" : "=r"(a) : "l"(p));
    return a;
}
__device__ __forceinline__ void ldsm_x4(uint32_t addr, uint32_t r[4]) {
    asm volatile("ldmatrix.sync.aligned.m8n8.x4.shared.b16 {%0,%1,%2,%3}, [%4];"
        : "=r"(r[0]), "=r"(r[1]), "=r"(r[2]), "=r"(r[3]) : "r"(addr));
}
__device__ __forceinline__ void ldsm_x2(uint32_t addr, uint32_t r[2]) {
    asm volatile("ldmatrix.sync.aligned.m8n8.x2.shared.b16 {%0,%1}, [%2];"
        : "=r"(r[0]), "=r"(r[1]) : "r"(addr));
}
__device__ __forceinline__ void mma16816h(float d[4], const uint32_t a[4],
                                          uint32_t b0, uint32_t b1) {
    asm volatile(
        "mma.sync.aligned.m16n8k16.row.col.f32.f16.f16.f32 "
        "{%0,%1,%2,%3}, {%4,%5,%6,%7}, {%8,%9}, {%0,%1,%2,%3};"
        : "+f"(d[0]), "+f"(d[1]), "+f"(d[2]), "+f"(d[3])
        : "r"(a[0]), "r"(a[1]), "r"(a[2]), "r"(a[3]), "r"(b0), "r"(b1));
}
__device__ __forceinline__ void cpasync16(uint32_t dst, const void* src) {
    asm volatile("cp.async.cg.shared.global [%0], [%1], 16;" :: "r"(dst), "l"(src));
}

// ---------------- embedding -> fp16, (t, b, k) padded to KP0 ----------------
__global__ __launch_bounds__(256) void k_embsplit(const int* __restrict__ tokens,
                                                  const float* __restrict__ emb) {
    int t = blockIdx.x;
    __shared__ int stok[NB];
    if (threadIdx.x < NB) stok[threadIdx.x] = tokens[t * NB + threadIdx.x];
    __syncthreads();
    size_t base = (size_t)t * NB * KP0;
    for (int idx = threadIdx.x; idx < NB * KP0; idx += 256) {
        int b = idx / KP0, k = idx - b * KP0;
        float v = (k < 200) ? __ldg(&emb[(size_t)stok[b] * 200 + k]) : 0.f;
        g_x[base + idx] = __float2half_rn(v);
    }
}

// ---------------- ALL weight prep (fp16 single) ----------------
__global__ __launch_bounds__(256) void k_prepw(
    const float* __restrict__ w0f, const float* __restrict__ w0b,
    const float* __restrict__ w1f, const float* __restrict__ w1b,
    const float* __restrict__ r0f, const float* __restrict__ r0b,
    const float* __restrict__ r1f, const float* __restrict__ r1b,
    const float* __restrict__ w1)
{
    int sel = blockIdx.y;
    int idx = blockIdx.x * 256 + threadIdx.x;
    if (sel < 4) {
        int layer = sel >> 1, dirv = sel & 1;
        const float* w = (sel == 0) ? w0f : (sel == 1) ? w0b : (sel == 2) ? w1f : w1b;
        int K = layer ? 400 : 200;
        int KPv = layer ? KP1 : KP0;
        if (idx >= 896 * KPv) return;
        __half* d = (layer ? g_w1 : g_w0) + (size_t)dirv * 896 * KPv;
        int m = idx / KPv, k = idx - m * KPv;
        float v = (m < 800 && k < K) ? __ldg(&w[(size_t)m * K + k]) : 0.f;
        d[idx] = __float2half_rn(v);
    } else if (sel < 8) {
        int layer = (sel - 4) >> 1, dirv = (sel - 4) & 1;
        const float* w = (sel == 4) ? r0f : (sel == 5) ? r0b : (sel == 6) ? r1f : r1b;
        if (idx >= 800 * KR) return;
        int r = idx / KR, k = idx - r * KR;
        int u = r >> 2, g = r & 3;
        float v = (k < 200) ? __ldg(&w[(size_t)(g * 200 + u) * 200 + k]) : 0.f;
        g_wr[((size_t)(layer * 2 + dirv) * 800 + r) * KR + k] = __float2half_rn(v);
    } else {
        if (idx >= 256 * KG) return;
        int n = idx / KG, kk = idx - n * KG;
        float v = 0.f;
        if (n < 200) {
            if (kk < 400) v = __ldg(&w1[(size_t)n * 800 + kk]);
            else if (kk >= 416 && kk < 816) v = __ldg(&w1[(size_t)n * 800 + kk - 16]);
        }
        g_w1p[idx] = __float2half_rn(v);
    }
}

// ---------------- tensor-core pre-GEMM (fp16 single) ----------------
__global__ __launch_bounds__(256) void k_gemm_mma(
    int layer,
    const float* __restrict__ bih_f, const float* __restrict__ bhh_f,
    const float* __restrict__ bih_b, const float* __restrict__ bhh_b)
{
    __shared__ __align__(16) __half sA[128 * AP];
    __shared__ __align__(16) __half sB[128 * AP];

    const int tid = threadIdx.x;
    const int warp = tid >> 5, lane = tid & 31;
    const int m0 = blockIdx.x * 128;
    const int t = blockIdx.y;
    const int dir = blockIdx.z;
    const int KPv = layer ? KP1 : KP0;
    const int nchunk = KPv >> 5;
    const __half* A = (layer ? g_w1 : g_w0) + (size_t)dir * 896 * KPv + (size_t)m0 * KPv;
    const __half* B = (layer ? g_h0 : g_x) + (size_t)t * NB * KPv;

    const int wm = (warp & 3) * 32;
    const int wn = (warp >> 2) * 64;
    const int lrow = lane & 15;
    const int lcol = (lane >> 4) * 8;

    const uint32_t aA = smem_u32(sA), aB = smem_u32(sB);

    float acc[2][8][4];
#pragma unroll
    for (int i = 0; i < 2; i++)
#pragma unroll
        for (int n = 0; n < 8; n++)
#pragma unroll
            for (int q = 0; q < 4; q++) acc[i][n][q] = 0.f;

    const int srow = tid >> 2;
    const int skv = (tid & 3) * 8;

    for (int c = 0; c < nchunk; c++) {
        const int kb0 = c * 32;
#pragma unroll
        for (int jv = 0; jv < 2; jv++) {
            int row = srow + jv * 64;
            size_t go = (size_t)row * KPv + kb0 + skv;
            int so = row * AP + skv;
            *(uint4*)&sA[so] = *(const uint4*)(A + go);
            *(uint4*)&sB[so] = *(const uint4*)(B + go);
        }
        __syncthreads();
#pragma unroll
        for (int ks = 0; ks < 2; ks++) {
            const int kb = ks * 16;
            uint32_t ah[2][4];
#pragma unroll
            for (int i = 0; i < 2; i++) {
                uint32_t off = (uint32_t)(((wm + i * 16 + lrow) * AP + kb + lcol) * 2);
                ldsm_x4(aA + off, ah[i]);
            }
#pragma unroll
            for (int p = 0; p < 4; p++) {
                uint32_t off = (uint32_t)(((wn + p * 16 + lrow) * AP + kb + lcol) * 2);
                uint32_t bh[4];
                ldsm_x4(aB + off, bh);
#pragma unroll
                for (int i = 0; i < 2; i++) {
                    mma16816h(acc[i][2 * p],     ah[i], bh[0], bh[2]);
                    mma16816h(acc[i][2 * p + 1], ah[i], bh[1], bh[3]);
                }
            }
        }
        __syncthreads();
    }

    const float* b1 = dir ? bih_b : bih_f;
    const float* b2 = dir ? bhh_b : bhh_f;
    float* outp = (dir ? g_pre_b : g_pre_f) + ((size_t)t * 800 + m0) * NB;
#pragma unroll
    for (int i = 0; i < 2; i++) {
#pragma unroll
        for (int half = 0; half < 2; half++) {
            int ml = wm + i * 16 + half * 8 + (lane >> 2);
            if (m0 + ml < 800) {
                float bs = __ldg(&b1[m0 + ml]) + __ldg(&b2[m0 + ml]);
                float* op = outp + (size_t)ml * NB + wn + (lane & 3) * 2;
#pragma unroll
                for (int n = 0; n < 8; n++) {
                    float2 v = make_float2(acc[i][n][half * 2] + bs,
                                           acc[i][n][half * 2 + 1] + bs);
                    *(float2*)(op + n * 8) = v;
                }
            }
        }
    }
}

// ---------------- barrier-free recurrence: batch-partitioned ----------------
// 32 CTAs = 2 dirs x 16 slices (8 batch cols). h lives in CTA smem (double buf),
// c in registers. W (800x208, interleaved rows u*4+g) streamed from L2 in 7
// chunks of 128 rows via a 3-buffer cp.async ring. pre loads directly into MMA
// accumulators (prefetched one chunk ahead). Gates fused per chunk.
// smem: W 3x55296 | sH 2x3456 @165888 | sD 2x(128x12 f32) @172800. total 185088.
#define RSMEM2 185088

__device__ __forceinline__ void stage_w_chunk(uint32_t sW, const __half* wr,
                                              int glx, int tid) {
    int m = glx % 7;
    uint32_t buf = sW + (uint32_t)(glx % 3) * 55296u;
    int cnt = ((m == 6) ? 32 : 128) * 26;
    const __half* src = wr + (size_t)(m * 128) * KR;
    for (int i = tid; i < cnt; i += 256) {
        int row = i / 26, seg = i - row * 26;
        cpasync16(buf + (uint32_t)((row * 216 + seg * 8) * 2),
                  src + (size_t)row * KR + seg * 8);
    }
    asm volatile("cp.async.commit_group;" ::: "memory");
}

__device__ __forceinline__ void load_pre_frag(const float* pre, int glx, int dir,
                                              int b0, int warp, int lane,
                                              float2& pa, float2& pb) {
    int m = glx % 7, sx = glx / 7;
    int tt = dir ? (511 - sx) : sx;
    int rbase = m * 128 + warp * 16;
    pa = make_float2(0.f, 0.f);
    pb = pa;
    if (rbase < 800) {
        int r = rbase + (lane >> 2);
        int prow0 = (r & 3) * 200 + (r >> 2);
        size_t base = (size_t)tt * 800 * NB + b0 + (lane & 3) * 2;
        pa = *(const float2*)&pre[base + (size_t)prow0 * NB];
        pb = *(const float2*)&pre[base + (size_t)(prow0 + 2) * NB];
    }
}

__global__ __launch_bounds__(256) void k_recur_mma(int layer)
{
    extern __shared__ __align__(16) char dsm[];
    const uint32_t sb = smem_u32(dsm);
    const uint32_t sW = sb;
    const uint32_t sH = sb + 165888u;
    float* sDb = (float*)(dsm + 172800);

    const int tid = threadIdx.x;
    const int warp = tid >> 5, lane = tid & 31;
    const int dir = blockIdx.x & 1;
    const int b0 = (blockIdx.x >> 1) * 8;
    const int lrow = lane & 15, lcol = (lane >> 4) * 8;

    const __half* wr = g_wr + (size_t)(layer * 2 + dir) * 800 * KR;
    const float* pre = dir ? g_pre_b : g_pre_f;

    // zero both h buffers (incl. k-pad [200,216))
    for (int i = tid; i < 1728; i += 256)
        ((uint32_t*)(dsm + 165888))[i] = 0u;

    float cc[7];
#pragma unroll
    for (int i = 0; i < 7; i++) cc[i] = 0.f;

    stage_w_chunk(sW, wr, 0, tid);
    stage_w_chunk(sW, wr, 1, tid);
    float2 pca, pcb, pna, pnb;
    load_pre_frag(pre, 0, dir, b0, warp, lane, pca, pcb);
    __syncthreads();

    const int lastGl = TT * 7 - 1;
    for (int s = 0; s < TT; s++) {
        const int t = dir ? (511 - s) : s;
        const uint32_t hcur = sH + (uint32_t)(s & 1) * 3456u;
        const uint32_t hnxt = sH + (uint32_t)((s + 1) & 1) * 3456u;
#pragma unroll
        for (int c = 0; c < 7; c++) {
            const int gl = s * 7 + c;
            if (gl == lastGl) { asm volatile("cp.async.wait_group 0;" ::: "memory"); }
            else              { asm volatile("cp.async.wait_group 1;" ::: "memory"); }
            __syncthreads();
            if (gl + 2 <= lastGl) stage_w_chunk(sW, wr, gl + 2, tid);
            if (gl + 1 <= lastGl) load_pre_frag(pre, gl + 1, dir, b0, warp, lane, pna, pnb);

            const int wrows = (c == 6) ? 32 : 128;
            const uint32_t wbuf = sW + (uint32_t)(gl % 3) * 55296u;
            float* sD = sDb + (size_t)(gl & 1) * 1536;

            if (warp * 16 < wrows) {
                float acc[4] = {pca.x, pca.y, pcb.x, pcb.y};
#pragma unroll
                for (int ko = 0; ko < 13; ko++) {
                    uint32_t a4[4], b2[2];
                    ldsm_x4(wbuf + (uint32_t)(((warp * 16 + lrow) * 216 + ko * 16 + lcol) * 2), a4);
                    ldsm_x2(hcur + (uint32_t)(((lane & 7) * 216 + ko * 16 + ((lane >> 3) & 1) * 8) * 2), b2);
                    mma16816h(acc, a4, b2[0], b2[1]);
                }
                int r0l = warp * 16 + (lane >> 2);
                int cl = (lane & 3) * 2;
                *(float2*)&sD[r0l * 12 + cl] = make_float2(acc[0], acc[1]);
                *(float2*)&sD[(r0l + 8) * 12 + cl] = make_float2(acc[2], acc[3]);
            }
            __syncthreads();

            // fused gate phase for this chunk's units (all 4 gates are local)
            if (tid < (wrows >> 2) * 8) {
                int uu = tid >> 3, col = tid & 7;
                float gi = sD[(4 * uu + 0) * 12 + col];
                float gf = sD[(4 * uu + 1) * 12 + col];
                float gg = sD[(4 * uu + 2) * 12 + col];
                float go = sD[(4 * uu + 3) * 12 + col];
                float cv = sigf(gf) * cc[c] + sigf(gi) * tanhfast(gg);
                cc[c] = cv;
                float hv = sigf(go) * tanhfast(cv);
                int ug = c * 32 + uu;
                *(__half*)(dsm + (hnxt - sb) + (col * 216 + ug) * 2) = __float2half_rn(hv);
            }
            pca = pna;
            pcb = pnb;
        }
        __syncthreads();
        // coalesced writeback of h(t) to the layer output
        if (tid < 200) {
            int col = tid / 25, seg = tid - col * 25;
            uint4 v = *(uint4*)(dsm + (hnxt - sb) + (col * 216 + seg * 8) * 2);
            if (layer == 0) {
                size_t o = ((size_t)t * NB + b0 + col) * KP1 + dir * 200 + seg * 8;
                *(uint4*)&g_h0[o] = v;
            } else {
                size_t o = ((size_t)(b0 + col) * TT + t) * 416 + dir * 200 + seg * 8;
                *(uint4*)&g_hbt[o] = v;
            }
        }
    }
}

// ---------------- tensor-core path-gather + MLP1 (tanh), fp16 single ----------------
__global__ __launch_bounds__(256) void k_gather_mma(
    const int* __restrict__ paths, const float* __restrict__ b1)
{
    __shared__ __align__(16) __half sA[128 * AP];
    __shared__ __align__(16) __half sB[128 * AP];
    __shared__ long long abase[128][2];

    const int tid = threadIdx.x;
    const int warp = tid >> 5, lane = tid & 31;
    const int s0 = blockIdx.x * 128;
    const int n0 = blockIdx.y * 128;

    {
        int i = tid >> 1, j = tid & 1;
        int s = s0 + i;
        int tval = paths[(size_t)s * 2 + j];
        int b = s >> 8;
        abase[i][j] = (tval >= 0) ? ((long long)b * TT + tval) * 416LL : -1LL;
    }
    __syncthreads();

    const int wm = (warp & 3) * 32;
    const int wn = (warp >> 2) * 64;
    const int lrow = lane & 15;
    const int lcol = (lane >> 4) * 8;

    const uint32_t aA = smem_u32(sA), aB = smem_u32(sB);

    float acc[2][8][4];
#pragma unroll
    for (int i = 0; i < 2; i++)
#pragma unroll
        for (int n = 0; n < 8; n++)
#pragma unroll
            for (int q = 0; q < 4; q++) acc[i][n][q] = 0.f;

    const int srow = tid >> 2;
    const int skv = (tid & 3) * 8;

    for (int c = 0; c < 26; c++) {
        const int j = (c >= 13) ? 1 : 0;
        const int kloc = c * 32 - j * 416 + skv;
        const int kb0 = c * 32;
#pragma unroll
        for (int jv = 0; jv < 2; jv++) {
            int row = srow + jv * 64;
            int so = row * AP + skv;
            long long ab = abase[row][j];
            uint4 vh = make_uint4(0u, 0u, 0u, 0u);
            if (ab >= 0) vh = *(const uint4*)(g_hbt + ab + kloc);
            *(uint4*)&sA[so] = vh;
            *(uint4*)&sB[so] = *(const uint4*)(g_w1p + (size_t)(n0 + row) * KG + kb0 + skv);
        }
        __syncthreads();
#pragma unroll
        for (int ks = 0; ks < 2; ks++) {
            const int kb = ks * 16;
            uint32_t ah[2][4];
#pragma unroll
            for (int i = 0; i < 2; i++) {
                uint32_t off = (uint32_t)(((wm + i * 16 + lrow) * AP + kb + lcol) * 2);
                ldsm_x4(aA + off, ah[i]);
            }
#pragma unroll
            for (int p = 0; p < 4; p++) {
                uint32_t off = (uint32_t)(((wn + p * 16 + lrow) * AP + kb + lcol) * 2);
                uint32_t bh[4];
                ldsm_x4(aB + off, bh);
#pragma unroll
                for (int i = 0; i < 2; i++) {
                    mma16816h(acc[i][2 * p],     ah[i], bh[0], bh[2]);
                    mma16816h(acc[i][2 * p + 1], ah[i], bh[1], bh[3]);
                }
            }
        }
        __syncthreads();
    }

#pragma unroll
    for (int i = 0; i < 2; i++) {
#pragma unroll
        for (int half = 0; half < 2; half++) {
            int ml = wm + i * 16 + half * 8 + (lane >> 2);
            int s = s0 + ml;
#pragma unroll
            for (int n = 0; n < 8; n++) {
                int nn = n0 + wn + (lane & 3) * 2 + n * 8;
                if (nn < 200) {
                    float2 v = make_float2(
                        tanhf(acc[i][n][half * 2] + __ldg(&b1[nn])),
                        tanhf(acc[i][n][half * 2 + 1] + __ldg(&b1[nn + 1])));
                    *(float2*)&g_hid[(size_t)s * 200 + nn] = v;
                }
            }
        }
    }
}

// ---------------- MLP2 + softmax: one warp per sample ----------------
__global__ __launch_bounds__(128) void k_mlp2(
    const float* __restrict__ w2, const float* __restrict__ b2, float* __restrict__ out)
{
    __shared__ float w2s[800];
    __shared__ float b2s[4];
    const int tid = threadIdx.x;
    for (int i = tid; i < 800; i += 128) w2s[i] = w2[i];
    if (tid < 4) b2s[tid] = b2[tid];
    __syncthreads();
    const int warp = tid >> 5, lane = tid & 31;
    const int s = blockIdx.x * 4 + warp;
    const float* hr = g_hid + (size_t)s * 200;
    float a0 = 0.f, a1 = 0.f, a2 = 0.f, a3 = 0.f;
    for (int k = lane; k < 200; k += 32) {
        float h = hr[k];
        a0 += h * w2s[k];
        a1 += h * w2s[200 + k];
        a2 += h * w2s[400 + k];
        a3 += h * w2s[600 + k];
    }
#pragma unroll
    for (int o = 16; o > 0; o >>= 1) {
        a0 += __shfl_down_sync(0xffffffffu, a0, o);
        a1 += __shfl_down_sync(0xffffffffu, a1, o);
        a2 += __shfl_down_sync(0xffffffffu, a2, o);
        a3 += __shfl_down_sync(0xffffffffu, a3, o);
    }
    if (lane == 0) {
        float l0 = a0 + b2s[0], l1 = a1 + b2s[1], l2 = a2 + b2s[2], l3 = a3 + b2s[3];
        float m = fmaxf(fmaxf(l0, l1), fmaxf(l2, l3));
        float e0 = expf(l0 - m), e1 = expf(l1 - m), e2 = expf(l2 - m), e3 = expf(l3 - m);
        float inv = 1.f / (e0 + e1 + e2 + e3);
        float4 r = make_float4(e0 * inv, e1 * inv, e2 * inv, e3 * inv);
        *(float4*)&out[(size_t)s * 4] = r;
    }
}

extern "C" void kernel_launch(void* const* d_in, const int* in_sizes, int n_in,
                              void* d_out, int out_size)
{
    const int* tokens = (const int*)d_in[0];
    const int* paths = (const int*)d_in[1];
    const float* emb = (const float*)d_in[2];
    const float* wih0f = (const float*)d_in[3];
    const float* whh0f = (const float*)d_in[4];
    const float* bih0f = (const float*)d_in[5];
    const float* bhh0f = (const float*)d_in[6];
    const float* wih0b = (const float*)d_in[7];
    const float* whh0b = (const float*)d_in[8];
    const float* bih0b = (const float*)d_in[9];
    const float* bhh0b = (const float*)d_in[10];
    const float* wih1f = (const float*)d_in[11];
    const float* whh1f = (const float*)d_in[12];
    const float* bih1f = (const float*)d_in[13];
    const float* bhh1f = (const float*)d_in[14];
    const float* wih1b = (const float*)d_in[15];
    const float* whh1b = (const float*)d_in[16];
    const float* bih1b = (const float*)d_in[17];
    const float* bhh1b = (const float*)d_in[18];
    const float* w1 = (const float*)d_in[19];
    const float* b1 = (const float*)d_in[20];
    const float* w2 = (const float*)d_in[21];
    const float* b2 = (const float*)d_in[22];
    float* out = (float*)d_out;

    cudaFuncSetAttribute(k_recur_mma, cudaFuncAttributeMaxDynamicSharedMemorySize, RSMEM2);

    k_embsplit<<<TT, 256>>>(tokens, emb);                               // launch 1
    dim3 gw((896 * KP1 + 255) / 256, 9);
    k_prepw<<<gw, 256>>>(wih0f, wih0b, wih1f, wih1b,
                         whh0f, whh0b, whh1f, whh1b, w1);               // launch 2

    dim3 gg(7, TT, 2);
    k_gemm_mma<<<gg, 256>>>(0, bih0f, bhh0f, bih0b, bhh0b);             // launch 3
    k_recur_mma<<<RCN2, 256, RSMEM2>>>(0);                              // launch 4 (profiled)
    k_gemm_mma<<<gg, 256>>>(1, bih1f, bhh1f, bih1b, bhh1b);             // launch 5
    k_recur_mma<<<RCN2, 256, RSMEM2>>>(1);                              // launch 6

    dim3 g4(NSAMP / 128, 2);
    k_gather_mma<<<g4, 256>>>(paths, b1);                               // launch 7
    k_mlp2<<<NSAMP / 4, 128>>>(w2, b2, out);                            // launch 8
}

// round 13
// speedup vs baseline: 1.4231x; 1.4231x over previous
#include <cuda_runtime.h>
#include <cuda_fp16.h>
#include <cstdint>

#define TT 512
#define NB 128
#define NSAMP 32768
#define KP0 224
#define KP1 416
#define AP 40    // GEMM smem stride (elems) for 32-wide k chunks
#define KR 208   // recurrence padded K (13 x k16)
#define KG 832   // gather-MLP padded K (2 x 416)

// ---------------- static scratch (no allocation; zero-initialized at load) -------
__device__ float g_pre_f[(size_t)TT * 800 * NB];   // (t, gate, b)
__device__ float g_pre_b[(size_t)TT * 800 * NB];
__device__ float g_hid[(size_t)NSAMP * 200];       // MLP hidden (s, n)

// fp16 single-precision operand buffers (error model calibrated round 10)
__device__ __align__(16) __half g_w0[(size_t)2 * 896 * KP0];  // [dir][m][k]
__device__ __align__(16) __half g_w1[(size_t)2 * 896 * KP1];
__device__ __align__(16) __half g_x[(size_t)TT * NB * KP0];   // (t, b, k)
__device__ __align__(16) __half g_h0[(size_t)TT * NB * KP1];  // layer0 out (t,b,k)
// layer1 out, (b, t, u) padded to 416; pad region [400,416) stays zero forever
__device__ __align__(16) __half g_hbt[(size_t)NB * TT * 416];
// w1 padded: [256 rows][KG]
__device__ __align__(16) __half g_w1p[(size_t)256 * KG];
// recurrence weights, interleaved rows (u*4+g), [layer][dir][800][KR]
__device__ __align__(16) __half g_wr[(size_t)2 * 2 * 800 * KR];
// h exchange: [group(8)][buf(2)][col(32)][208 units]; pad [200,208) stays zero
__device__ __align__(16) __half g_hx[(size_t)8 * 2 * 32 * 208];
// per-step arrival counters [group(8)][512]
__device__ unsigned g_rcnt[8 * 512];
__device__ unsigned g_barC2, g_barG2;

// ---------------- helpers ----------------
__device__ __forceinline__ float sigf(float x) { return 1.f / (1.f + __expf(-x)); }
__device__ __forceinline__ float tanhfast(float x) {
    float e = __expf(-2.f * x);
    return (1.f - e) * (1.f / (1.f + e));
}
__device__ __forceinline__ uint32_t smem_u32(const void* p) {
    uint32_t a;
    asm("{ .reg .u64 t; cvta.to.shared.u64 t, %1; cvt.u32.u64 %0, t; }" : "=r"(a) : "l"(p));
    return a;
}
__device__ __forceinline__ void ldsm_x4(uint32_t addr, uint32_t r[4]) {
    asm volatile("ldmatrix.sync.aligned.m8n8.x4.shared.b16 {%0,%1,%2,%3}, [%4];"
        : "=r"(r[0]), "=r"(r[1]), "=r"(r[2]), "=r"(r[3]) : "r"(addr));
}
__device__ __forceinline__ void mma16816h(float d[4], const uint32_t a[4],
                                          uint32_t b0, uint32_t b1) {
    asm volatile(
        "mma.sync.aligned.m16n8k16.row.col.f32.f16.f16.f32 "
        "{%0,%1,%2,%3}, {%4,%5,%6,%7}, {%8,%9}, {%0,%1,%2,%3};"
        : "+f"(d[0]), "+f"(d[1]), "+f"(d[2]), "+f"(d[3])
        : "r"(a[0]), "r"(a[1]), "r"(a[2]), "r"(a[3]), "r"(b0), "r"(b1));
}
__device__ __forceinline__ void cpasync16(uint32_t dst, const void* src) {
    asm volatile("cp.async.cg.shared.global [%0], [%1], 16;" :: "r"(dst), "l"(src));
}

// ---------------- embedding -> fp16, (t, b, k) padded to KP0 ----------------
__global__ __launch_bounds__(256) void k_embsplit(const int* __restrict__ tokens,
                                                  const float* __restrict__ emb) {
    int t = blockIdx.x;
    __shared__ int stok[NB];
    if (threadIdx.x < NB) stok[threadIdx.x] = tokens[t * NB + threadIdx.x];
    __syncthreads();
    size_t base = (size_t)t * NB * KP0;
    for (int idx = threadIdx.x; idx < NB * KP0; idx += 256) {
        int b = idx / KP0, k = idx - b * KP0;
        float v = (k < 200) ? __ldg(&emb[(size_t)stok[b] * 200 + k]) : 0.f;
        g_x[base + idx] = __float2half_rn(v);
    }
}

// ---------------- ALL weight prep (fp16 single) ----------------
__global__ __launch_bounds__(256) void k_prepw(
    const float* __restrict__ w0f, const float* __restrict__ w0b,
    const float* __restrict__ w1f, const float* __restrict__ w1b,
    const float* __restrict__ r0f, const float* __restrict__ r0b,
    const float* __restrict__ r1f, const float* __restrict__ r1b,
    const float* __restrict__ w1)
{
    int sel = blockIdx.y;
    int idx = blockIdx.x * 256 + threadIdx.x;
    if (sel < 4) {
        int layer = sel >> 1, dirv = sel & 1;
        const float* w = (sel == 0) ? w0f : (sel == 1) ? w0b : (sel == 2) ? w1f : w1b;
        int K = layer ? 400 : 200;
        int KPv = layer ? KP1 : KP0;
        if (idx >= 896 * KPv) return;
        __half* d = (layer ? g_w1 : g_w0) + (size_t)dirv * 896 * KPv;
        int m = idx / KPv, k = idx - m * KPv;
        float v = (m < 800 && k < K) ? __ldg(&w[(size_t)m * K + k]) : 0.f;
        d[idx] = __float2half_rn(v);
    } else if (sel < 8) {
        int layer = (sel - 4) >> 1, dirv = (sel - 4) & 1;
        const float* w = (sel == 4) ? r0f : (sel == 5) ? r0b : (sel == 6) ? r1f : r1b;
        if (idx >= 800 * KR) return;
        int r = idx / KR, k = idx - r * KR;
        int u = r >> 2, g = r & 3;
        float v = (k < 200) ? __ldg(&w[(size_t)(g * 200 + u) * 200 + k]) : 0.f;
        g_wr[((size_t)(layer * 2 + dirv) * 800 + r) * KR + k] = __float2half_rn(v);
    } else {
        if (idx >= 256 * KG) return;
        int n = idx / KG, kk = idx - n * KG;
        float v = 0.f;
        if (n < 200) {
            if (kk < 400) v = __ldg(&w1[(size_t)n * 800 + kk]);
            else if (kk >= 416 && kk < 816) v = __ldg(&w1[(size_t)n * 800 + kk - 16]);
        }
        g_w1p[idx] = __float2half_rn(v);
    }
}

// ---------------- tensor-core pre-GEMM (fp16 single) ----------------
__global__ __launch_bounds__(256) void k_gemm_mma(
    int layer,
    const float* __restrict__ bih_f, const float* __restrict__ bhh_f,
    const float* __restrict__ bih_b, const float* __restrict__ bhh_b)
{
    __shared__ __align__(16) __half sA[128 * AP];
    __shared__ __align__(16) __half sB[128 * AP];

    const int tid = threadIdx.x;
    const int warp = tid >> 5, lane = tid & 31;
    const int m0 = blockIdx.x * 128;
    const int t = blockIdx.y;
    const int dir = blockIdx.z;
    const int KPv = layer ? KP1 : KP0;
    const int nchunk = KPv >> 5;
    const __half* A = (layer ? g_w1 : g_w0) + (size_t)dir * 896 * KPv + (size_t)m0 * KPv;
    const __half* B = (layer ? g_h0 : g_x) + (size_t)t * NB * KPv;

    const int wm = (warp & 3) * 32;
    const int wn = (warp >> 2) * 64;
    const int lrow = lane & 15;
    const int lcol = (lane >> 4) * 8;

    const uint32_t aA = smem_u32(sA), aB = smem_u32(sB);

    float acc[2][8][4];
#pragma unroll
    for (int i = 0; i < 2; i++)
#pragma unroll
        for (int n = 0; n < 8; n++)
#pragma unroll
            for (int q = 0; q < 4; q++) acc[i][n][q] = 0.f;

    const int srow = tid >> 2;
    const int skv = (tid & 3) * 8;

    for (int c = 0; c < nchunk; c++) {
        const int kb0 = c * 32;
#pragma unroll
        for (int jv = 0; jv < 2; jv++) {
            int row = srow + jv * 64;
            size_t go = (size_t)row * KPv + kb0 + skv;
            int so = row * AP + skv;
            *(uint4*)&sA[so] = *(const uint4*)(A + go);
            *(uint4*)&sB[so] = *(const uint4*)(B + go);
        }
        __syncthreads();
#pragma unroll
        for (int ks = 0; ks < 2; ks++) {
            const int kb = ks * 16;
            uint32_t ah[2][4];
#pragma unroll
            for (int i = 0; i < 2; i++) {
                uint32_t off = (uint32_t)(((wm + i * 16 + lrow) * AP + kb + lcol) * 2);
                ldsm_x4(aA + off, ah[i]);
            }
#pragma unroll
            for (int p = 0; p < 4; p++) {
                uint32_t off = (uint32_t)(((wn + p * 16 + lrow) * AP + kb + lcol) * 2);
                uint32_t bh[4];
                ldsm_x4(aB + off, bh);
#pragma unroll
                for (int i = 0; i < 2; i++) {
                    mma16816h(acc[i][2 * p],     ah[i], bh[0], bh[2]);
                    mma16816h(acc[i][2 * p + 1], ah[i], bh[1], bh[3]);
                }
            }
        }
        __syncthreads();
    }

    const float* b1 = dir ? bih_b : bih_f;
    const float* b2 = dir ? bhh_b : bhh_f;
    float* outp = (dir ? g_pre_b : g_pre_f) + ((size_t)t * 800 + m0) * NB;
#pragma unroll
    for (int i = 0; i < 2; i++) {
#pragma unroll
        for (int half = 0; half < 2; half++) {
            int ml = wm + i * 16 + half * 8 + (lane >> 2);
            if (m0 + ml < 800) {
                float bs = __ldg(&b1[m0 + ml]) + __ldg(&b2[m0 + ml]);
                float* op = outp + (size_t)ml * NB + wn + (lane & 3) * 2;
#pragma unroll
                for (int n = 0; n < 8; n++) {
                    float2 v = make_float2(acc[i][n][half * 2] + bs,
                                           acc[i][n][half * 2 + 1] + bs);
                    *(float2*)(op + n * 8) = v;
                }
            }
        }
    }
}

// ---------------- 2D-partitioned recurrence: 32 CTAs = 2 dir x 4 bslice x 4 ugroup
// Each CTA: 50 units (200 W rows resident in smem) x 32 batch cols. h exchanged
// among the 4 CTAs of (dir,bslice) via small gmem buffer + per-step counters.
// smem: W [208][216] f16 @0 (89856) | hcur [32][216] f16 @89856 (13824) |
//       D [208][33] f32 @103680 (27456) | hsm [32][52] f16 @131136 (3328) = 134464
#define RS_H 89856
#define RS_D 103680
#define RS_HS 131136
#define RSMEM2 134464
__global__ __launch_bounds__(256) void k_recur_mma(int layer)
{
    extern __shared__ __align__(16) char dsm[];
    const uint32_t sb = smem_u32(dsm);
    const uint32_t sW = sb;
    const uint32_t sH = sb + RS_H;
    float* Dsm = (float*)(dsm + RS_D);
    __half* hsm = (__half*)(dsm + RS_HS);

    const int tid = threadIdx.x;
    const int warp = tid >> 5, lane = tid & 31;
    const int dir = blockIdx.x & 1;
    const int bs = (blockIdx.x >> 1) & 3;
    const int ug = blockIdx.x >> 3;
    const int b0 = bs * 32;
    const int grp = dir * 4 + bs;
    const int lrow = lane & 15, lcol = (lane >> 4) * 8;

    const __half* wr = g_wr + ((size_t)(layer * 2 + dir) * 800 + (size_t)ug * 200) * KR;
    const float* pre = dir ? g_pre_b : g_pre_f;
    __half* hx = g_hx + (size_t)grp * 2 * 32 * 208;
    unsigned* cnt = g_rcnt + grp * 512;

    // zero my share of counters + group h buffers (graph replays reuse them)
    if (tid < 128) cnt[ug * 128 + tid] = 0u;
    {
        uint32_t* hz = (uint32_t*)hx;
        for (int i = tid; i < 1664; i += 256) hz[ug * 1664 + i] = 0u;
    }
    // stage resident W (200 rows x 208) + zero pad rows 200..207
    for (int i = tid; i < 5200; i += 256) {
        int r = i / 26, seg = i - r * 26;
        cpasync16(sW + (uint32_t)((r * 216 + seg * 8) * 2), wr + (size_t)r * KR + seg * 8);
    }
    asm volatile("cp.async.commit_group;" ::: "memory");
    for (int i = tid; i < 864; i += 256)
        ((uint32_t*)(dsm + 200 * 216 * 2))[i] = 0u;

    // entry barrier over all 32 CTAs (orders the zeroing before any arrivals)
    __threadfence();
    __syncthreads();
    if (tid == 0) {
        unsigned gen = *(volatile unsigned*)&g_barG2;
        unsigned a = atomicAdd(&g_barC2, 1u);
        if (a == 31u) {
            atomicExch(&g_barC2, 0u);
            __threadfence();
            atomicAdd(&g_barG2, 1u);
        } else {
            volatile unsigned* vg = &g_barG2;
            while (*vg == gen) {}
        }
        __threadfence();
    }
    __syncthreads();

    float cc[7];
#pragma unroll
    for (int i = 0; i < 7; i++) cc[i] = 0.f;

    for (int s = 0; s < TT; s++) {
        const int t = dir ? (TT - 1 - s) : s;

        if (s > 0) {
            if (tid == 0) {
                unsigned v;
                do {
                    asm volatile("ld.acquire.gpu.global.u32 %0, [%1];"
                                 : "=r"(v) : "l"(cnt + (s - 1)) : "memory");
                } while (v < 4u);
            }
            __syncthreads();
        }
        // stage hcur (32 cols x 208 units)
        const __half* hsrc = hx + (size_t)(s & 1) * 32 * 208;
        for (int i = tid; i < 832; i += 256) {
            int r = i / 26, seg = i - r * 26;
            cpasync16(sH + (uint32_t)((r * 216 + seg * 8) * 2),
                      hsrc + (size_t)r * 208 + seg * 8);
        }
        asm volatile("cp.async.commit_group;" ::: "memory");

        // pre-activations loaded directly as accumulator init (overlaps staging)
        float acc[2][4][4];
        const float* pt = pre + (size_t)t * 800 * NB + b0;
#pragma unroll
        for (int tt = 0; tt < 2; tt++) {
            int T = (tt == 0) ? warp : warp + 8;
            bool va = (tt == 0) || (warp < 5);
#pragma unroll
            for (int p = 0; p < 4; p++) {
                int c = p * 8 + (lane & 3) * 2;
#pragma unroll
                for (int hh = 0; hh < 2; hh++) {
                    int r = T * 16 + (lane >> 2) + hh * 8;
                    float2 v = make_float2(0.f, 0.f);
                    if (va && r < 200) {
                        int prow = (r & 3) * 200 + ug * 50 + (r >> 2);
                        v = *(const float2*)&pt[(size_t)prow * NB + c];
                    }
                    acc[tt][p][hh * 2] = v.x;
                    acc[tt][p][hh * 2 + 1] = v.y;
                }
            }
        }

        asm volatile("cp.async.wait_group 0;" ::: "memory");
        __syncthreads();

        // MMA: D[208x32] = W @ h ; warp w handles M-tiles w and w+8 (w<5)
#pragma unroll
        for (int ko = 0; ko < 13; ko++) {
            uint32_t bf0[4], bf1[4];
            ldsm_x4(sH + (uint32_t)((lrow * 216 + ko * 16 + lcol) * 2), bf0);
            ldsm_x4(sH + (uint32_t)(((16 + lrow) * 216 + ko * 16 + lcol) * 2), bf1);
            {
                uint32_t a4[4];
                ldsm_x4(sW + (uint32_t)(((warp * 16 + lrow) * 216 + ko * 16 + lcol) * 2), a4);
                mma16816h(acc[0][0], a4, bf0[0], bf0[2]);
                mma16816h(acc[0][1], a4, bf0[1], bf0[3]);
                mma16816h(acc[0][2], a4, bf1[0], bf1[2]);
                mma16816h(acc[0][3], a4, bf1[1], bf1[3]);
            }
            if (warp < 5) {
                uint32_t a4[4];
                ldsm_x4(sW + (uint32_t)((((warp + 8) * 16 + lrow) * 216 + ko * 16 + lcol) * 2), a4);
                mma16816h(acc[1][0], a4, bf0[0], bf0[2]);
                mma16816h(acc[1][1], a4, bf0[1], bf0[3]);
                mma16816h(acc[1][2], a4, bf1[0], bf1[2]);
                mma16816h(acc[1][3], a4, bf1[1], bf1[3]);
            }
        }
        // D -> smem (stride 33)
#pragma unroll
        for (int tt = 0; tt < 2; tt++) {
            if (tt == 1 && warp >= 5) break;
            int T = (tt == 0) ? warp : warp + 8;
            int r = T * 16 + (lane >> 2);
#pragma unroll
            for (int p = 0; p < 4; p++) {
                int c = p * 8 + (lane & 3) * 2;
                Dsm[r * 33 + c] = acc[tt][p][0];
                Dsm[r * 33 + c + 1] = acc[tt][p][1];
                Dsm[(r + 8) * 33 + c] = acc[tt][p][2];
                Dsm[(r + 8) * 33 + c + 1] = acc[tt][p][3];
            }
        }
        __syncthreads();

        // gates: item i = (u_local, col); c-state per-thread registers
#pragma unroll
        for (int k = 0; k < 7; k++) {
            int i = tid + k * 256;
            if (i < 1600) {
                int ul = i >> 5, col = i & 31;
                float gi = Dsm[(ul * 4 + 0) * 33 + col];
                float gf = Dsm[(ul * 4 + 1) * 33 + col];
                float gg = Dsm[(ul * 4 + 2) * 33 + col];
                float go = Dsm[(ul * 4 + 3) * 33 + col];
                float cv = sigf(gf) * cc[k] + sigf(gi) * tanhfast(gg);
                cc[k] = cv;
                hsm[col * 52 + ul] = __float2half_rn(sigf(go) * tanhfast(cv));
            }
        }
        __syncthreads();

        // write-out: group buffer + layer output (u32 granularity, 4-aligned)
        {
            __half* hdst = hx + (size_t)((s + 1) & 1) * 32 * 208 + ug * 50;
            for (int i = tid; i < 800; i += 256) {
                int col = i / 25, q = i - col * 25;
                uint32_t v = *(uint32_t*)&hsm[col * 52 + q * 2];
                *(uint32_t*)(hdst + (size_t)col * 208 + q * 2) = v;
                if (layer == 0) {
                    size_t o = ((size_t)t * NB + b0 + col) * KP1 + dir * 200 + ug * 50 + q * 2;
                    *(uint32_t*)&g_h0[o] = v;
                } else {
                    size_t o = ((size_t)(b0 + col) * TT + t) * 416 + dir * 200 + ug * 50 + q * 2;
                    *(uint32_t*)&g_hbt[o] = v;
                }
            }
        }
        __threadfence();
        __syncthreads();
        if (tid == 0)
            asm volatile("red.release.gpu.global.add.u32 [%0], 1;"
                         :: "l"(cnt + s) : "memory");
    }
}

// ---------------- tensor-core path-gather + MLP1 (tanh), fp16 single ----------------
__global__ __launch_bounds__(256) void k_gather_mma(
    const int* __restrict__ paths, const float* __restrict__ b1)
{
    __shared__ __align__(16) __half sA[128 * AP];
    __shared__ __align__(16) __half sB[128 * AP];
    __shared__ long long abase[128][2];

    const int tid = threadIdx.x;
    const int warp = tid >> 5, lane = tid & 31;
    const int s0 = blockIdx.x * 128;
    const int n0 = blockIdx.y * 128;

    {
        int i = tid >> 1, j = tid & 1;
        int s = s0 + i;
        int tval = paths[(size_t)s * 2 + j];
        int b = s >> 8;
        abase[i][j] = (tval >= 0) ? ((long long)b * TT + tval) * 416LL : -1LL;
    }
    __syncthreads();

    const int wm = (warp & 3) * 32;
    const int wn = (warp >> 2) * 64;
    const int lrow = lane & 15;
    const int lcol = (lane >> 4) * 8;

    const uint32_t aA = smem_u32(sA), aB = smem_u32(sB);

    float acc[2][8][4];
#pragma unroll
    for (int i = 0; i < 2; i++)
#pragma unroll
        for (int n = 0; n < 8; n++)
#pragma unroll
            for (int q = 0; q < 4; q++) acc[i][n][q] = 0.f;

    const int srow = tid >> 2;
    const int skv = (tid & 3) * 8;

    for (int c = 0; c < 26; c++) {
        const int j = (c >= 13) ? 1 : 0;
        const int kloc = c * 32 - j * 416 + skv;
        const int kb0 = c * 32;
#pragma unroll
        for (int jv = 0; jv < 2; jv++) {
            int row = srow + jv * 64;
            int so = row * AP + skv;
            long long ab = abase[row][j];
            uint4 vh = make_uint4(0u, 0u, 0u, 0u);
            if (ab >= 0) vh = *(const uint4*)(g_hbt + ab + kloc);
            *(uint4*)&sA[so] = vh;
            *(uint4*)&sB[so] = *(const uint4*)(g_w1p + (size_t)(n0 + row) * KG + kb0 + skv);
        }
        __syncthreads();
#pragma unroll
        for (int ks = 0; ks < 2; ks++) {
            const int kb = ks * 16;
            uint32_t ah[2][4];
#pragma unroll
            for (int i = 0; i < 2; i++) {
                uint32_t off = (uint32_t)(((wm + i * 16 + lrow) * AP + kb + lcol) * 2);
                ldsm_x4(aA + off, ah[i]);
            }
#pragma unroll
            for (int p = 0; p < 4; p++) {
                uint32_t off = (uint32_t)(((wn + p * 16 + lrow) * AP + kb + lcol) * 2);
                uint32_t bh[4];
                ldsm_x4(aB + off, bh);
#pragma unroll
                for (int i = 0; i < 2; i++) {
                    mma16816h(acc[i][2 * p],     ah[i], bh[0], bh[2]);
                    mma16816h(acc[i][2 * p + 1], ah[i], bh[1], bh[3]);
                }
            }
        }
        __syncthreads();
    }

#pragma unroll
    for (int i = 0; i < 2; i++) {
#pragma unroll
        for (int half = 0; half < 2; half++) {
            int ml = wm + i * 16 + half * 8 + (lane >> 2);
            int s = s0 + ml;
#pragma unroll
            for (int n = 0; n < 8; n++) {
                int nn = n0 + wn + (lane & 3) * 2 + n * 8;
                if (nn < 200) {
                    float2 v = make_float2(
                        tanhf(acc[i][n][half * 2] + __ldg(&b1[nn])),
                        tanhf(acc[i][n][half * 2 + 1] + __ldg(&b1[nn + 1])));
                    *(float2*)&g_hid[(size_t)s * 200 + nn] = v;
                }
            }
        }
    }
}

// ---------------- MLP2 + softmax: one warp per sample ----------------
__global__ __launch_bounds__(128) void k_mlp2(
    const float* __restrict__ w2, const float* __restrict__ b2, float* __restrict__ out)
{
    __shared__ float w2s[800];
    __shared__ float b2s[4];
    const int tid = threadIdx.x;
    for (int i = tid; i < 800; i += 128) w2s[i] = w2[i];
    if (tid < 4) b2s[tid] = b2[tid];
    __syncthreads();
    const int warp = tid >> 5, lane = tid & 31;
    const int s = blockIdx.x * 4 + warp;
    const float* hr = g_hid + (size_t)s * 200;
    float a0 = 0.f, a1 = 0.f, a2 = 0.f, a3 = 0.f;
    for (int k = lane; k < 200; k += 32) {
        float h = hr[k];
        a0 += h * w2s[k];
        a1 += h * w2s[200 + k];
        a2 += h * w2s[400 + k];
        a3 += h * w2s[600 + k];
    }
#pragma unroll
    for (int o = 16; o > 0; o >>= 1) {
        a0 += __shfl_down_sync(0xffffffffu, a0, o);
        a1 += __shfl_down_sync(0xffffffffu, a1, o);
        a2 += __shfl_down_sync(0xffffffffu, a2, o);
        a3 += __shfl_down_sync(0xffffffffu, a3, o);
    }
    if (lane == 0) {
        float l0 = a0 + b2s[0], l1 = a1 + b2s[1], l2 = a2 + b2s[2], l3 = a3 + b2s[3];
        float m = fmaxf(fmaxf(l0, l1), fmaxf(l2, l3));
        float e0 = expf(l0 - m), e1 = expf(l1 - m), e2 = expf(l2 - m), e3 = expf(l3 - m);
        float inv = 1.f / (e0 + e1 + e2 + e3);
        float4 r = make_float4(e0 * inv, e1 * inv, e2 * inv, e3 * inv);
        *(float4*)&out[(size_t)s * 4] = r;
    }
}

extern "C" void kernel_launch(void* const* d_in, const int* in_sizes, int n_in,
                              void* d_out, int out_size)
{
    const int* tokens = (const int*)d_in[0];
    const int* paths = (const int*)d_in[1];
    const float* emb = (const float*)d_in[2];
    const float* wih0f = (const float*)d_in[3];
    const float* whh0f = (const float*)d_in[4];
    const float* bih0f = (const float*)d_in[5];
    const float* bhh0f = (const float*)d_in[6];
    const float* wih0b = (const float*)d_in[7];
    const float* whh0b = (const float*)d_in[8];
    const float* bih0b = (const float*)d_in[9];
    const float* bhh0b = (const float*)d_in[10];
    const float* wih1f = (const float*)d_in[11];
    const float* whh1f = (const float*)d_in[12];
    const float* bih1f = (const float*)d_in[13];
    const float* bhh1f = (const float*)d_in[14];
    const float* wih1b = (const float*)d_in[15];
    const float* whh1b = (const float*)d_in[16];
    const float* bih1b = (const float*)d_in[17];
    const float* bhh1b = (const float*)d_in[18];
    const float* w1 = (const float*)d_in[19];
    const float* b1 = (const float*)d_in[20];
    const float* w2 = (const float*)d_in[21];
    const float* b2 = (const float*)d_in[22];
    float* out = (float*)d_out;

    cudaFuncSetAttribute(k_recur_mma, cudaFuncAttributeMaxDynamicSharedMemorySize, RSMEM2);

    k_embsplit<<<TT, 256>>>(tokens, emb);                               // launch 1
    dim3 gw((896 * KP1 + 255) / 256, 9);
    k_prepw<<<gw, 256>>>(wih0f, wih0b, wih1f, wih1b,
                         whh0f, whh0b, whh1f, whh1b, w1);               // launch 2

    dim3 gg(7, TT, 2);
    k_gemm_mma<<<gg, 256>>>(0, bih0f, bhh0f, bih0b, bhh0b);             // launch 3
    k_recur_mma<<<32, 256, RSMEM2>>>(0);                                // launch 4 (profiled)
    k_gemm_mma<<<gg, 256>>>(1, bih1f, bhh1f, bih1b, bhh1b);             // launch 5
    k_recur_mma<<<32, 256, RSMEM2>>>(1);                                // launch 6

    dim3 g4(NSAMP / 128, 2);
    k_gather_mma<<<g4, 256>>>(paths, b1);                               // launch 7
    k_mlp2<<<NSAMP / 4, 128>>>(w2, b2, out);                            // launch 8
}

// round 14
// speedup vs baseline: 1.5595x; 1.0958x over previous
#include <cuda_runtime.h>
#include <cuda_fp16.h>
#include <cstdint>

#define TT 512
#define NB 128
#define NSAMP 32768
#define KP0 224
#define KP1 416
#define AP 40    // GEMM smem stride (elems) for 32-wide k chunks
#define KR 208   // recurrence padded K (13 x k16)
#define KG 832   // gather-MLP padded K (2 x 416)

// ---------------- static scratch (no allocation; zero-initialized at load) -------
__device__ float g_pre_f[(size_t)TT * 800 * NB];   // (t, gate, b)
__device__ float g_pre_b[(size_t)TT * 800 * NB];
__device__ float g_hid[(size_t)NSAMP * 200];       // MLP hidden (s, n)

// fp16 single-precision operand buffers (error model calibrated round 10)
__device__ __align__(16) __half g_w0[(size_t)2 * 896 * KP0];  // [dir][m][k]
__device__ __align__(16) __half g_w1[(size_t)2 * 896 * KP1];
__device__ __align__(16) __half g_x[(size_t)TT * NB * KP0];   // (t, b, k)
__device__ __align__(16) __half g_h0[(size_t)TT * NB * KP1];  // layer0 out (t,b,k)
// layer1 out, (b, t, u) padded to 416; pad region [400,416) stays zero forever
__device__ __align__(16) __half g_hbt[(size_t)NB * TT * 416];
// w1 padded: [256 rows][KG]
__device__ __align__(16) __half g_w1p[(size_t)256 * KG];
// recurrence weights, interleaved rows (u*4+g), [layer][dir][800][KR]
__device__ __align__(16) __half g_wr[(size_t)2 * 2 * 800 * KR];

// ---------------- helpers ----------------
__device__ __forceinline__ float sigf(float x) { return 1.f / (1.f + __expf(-x)); }
__device__ __forceinline__ float tanhfast(float x) {
    float e = __expf(-2.f * x);
    return (1.f - e) * (1.f / (1.f + e));
}
__device__ __forceinline__ uint32_t smem_u32(const void* p) {
    uint32_t a;
    asm("{ .reg .u64 t; cvta.to.shared.u64 t, %1; cvt.u32.u64 %0, t; }" : "=r"(a) : "l"(p));
    return a;
}
__device__ __forceinline__ void ldsm_x4(uint32_t addr, uint32_t r[4]) {
    asm volatile("ldmatrix.sync.aligned.m8n8.x4.shared.b16 {%0,%1,%2,%3}, [%4];"
        : "=r"(r[0]), "=r"(r[1]), "=r"(r[2]), "=r"(r[3]) : "r"(addr));
}
__device__ __forceinline__ void mma16816h(float d[4], const uint32_t a[4],
                                          uint32_t b0, uint32_t b1) {
    asm volatile(
        "mma.sync.aligned.m16n8k16.row.col.f32.f16.f16.f32 "
        "{%0,%1,%2,%3}, {%4,%5,%6,%7}, {%8,%9}, {%0,%1,%2,%3};"
        : "+f"(d[0]), "+f"(d[1]), "+f"(d[2]), "+f"(d[3])
        : "r"(a[0]), "r"(a[1]), "r"(a[2]), "r"(a[3]), "r"(b0), "r"(b1));
}
__device__ __forceinline__ void cpasync16(uint32_t dst, const void* src) {
    asm volatile("cp.async.cg.shared.global [%0], [%1], 16;" :: "r"(dst), "l"(src));
}

// ---------------- embedding -> fp16, (t, b, k) padded to KP0 ----------------
__global__ __launch_bounds__(256) void k_embsplit(const int* __restrict__ tokens,
                                                  const float* __restrict__ emb) {
    int t = blockIdx.x;
    __shared__ int stok[NB];
    if (threadIdx.x < NB) stok[threadIdx.x] = tokens[t * NB + threadIdx.x];
    __syncthreads();
    size_t base = (size_t)t * NB * KP0;
    for (int idx = threadIdx.x; idx < NB * KP0; idx += 256) {
        int b = idx / KP0, k = idx - b * KP0;
        float v = (k < 200) ? __ldg(&emb[(size_t)stok[b] * 200 + k]) : 0.f;
        g_x[base + idx] = __float2half_rn(v);
    }
}

// ---------------- ALL weight prep (fp16 single) ----------------
__global__ __launch_bounds__(256) void k_prepw(
    const float* __restrict__ w0f, const float* __restrict__ w0b,
    const float* __restrict__ w1f, const float* __restrict__ w1b,
    const float* __restrict__ r0f, const float* __restrict__ r0b,
    const float* __restrict__ r1f, const float* __restrict__ r1b,
    const float* __restrict__ w1)
{
    int sel = blockIdx.y;
    int idx = blockIdx.x * 256 + threadIdx.x;
    if (sel < 4) {
        int layer = sel >> 1, dirv = sel & 1;
        const float* w = (sel == 0) ? w0f : (sel == 1) ? w0b : (sel == 2) ? w1f : w1b;
        int K = layer ? 400 : 200;
        int KPv = layer ? KP1 : KP0;
        if (idx >= 896 * KPv) return;
        __half* d = (layer ? g_w1 : g_w0) + (size_t)dirv * 896 * KPv;
        int m = idx / KPv, k = idx - m * KPv;
        float v = (m < 800 && k < K) ? __ldg(&w[(size_t)m * K + k]) : 0.f;
        d[idx] = __float2half_rn(v);
    } else if (sel < 8) {
        int layer = (sel - 4) >> 1, dirv = (sel - 4) & 1;
        const float* w = (sel == 4) ? r0f : (sel == 5) ? r0b : (sel == 6) ? r1f : r1b;
        if (idx >= 800 * KR) return;
        int r = idx / KR, k = idx - r * KR;
        int u = r >> 2, g = r & 3;
        float v = (k < 200) ? __ldg(&w[(size_t)(g * 200 + u) * 200 + k]) : 0.f;
        g_wr[((size_t)(layer * 2 + dirv) * 800 + r) * KR + k] = __float2half_rn(v);
    } else {
        if (idx >= 256 * KG) return;
        int n = idx / KG, kk = idx - n * KG;
        float v = 0.f;
        if (n < 200) {
            if (kk < 400) v = __ldg(&w1[(size_t)n * 800 + kk]);
            else if (kk >= 416 && kk < 816) v = __ldg(&w1[(size_t)n * 800 + kk - 16]);
        }
        g_w1p[idx] = __float2half_rn(v);
    }
}

// ---------------- tensor-core pre-GEMM (fp16 single) ----------------
__global__ __launch_bounds__(256) void k_gemm_mma(
    int layer,
    const float* __restrict__ bih_f, const float* __restrict__ bhh_f,
    const float* __restrict__ bih_b, const float* __restrict__ bhh_b)
{
    __shared__ __align__(16) __half sA[128 * AP];
    __shared__ __align__(16) __half sB[128 * AP];

    const int tid = threadIdx.x;
    const int warp = tid >> 5, lane = tid & 31;
    const int m0 = blockIdx.x * 128;
    const int t = blockIdx.y;
    const int dir = blockIdx.z;
    const int KPv = layer ? KP1 : KP0;
    const int nchunk = KPv >> 5;
    const __half* A = (layer ? g_w1 : g_w0) + (size_t)dir * 896 * KPv + (size_t)m0 * KPv;
    const __half* B = (layer ? g_h0 : g_x) + (size_t)t * NB * KPv;

    const int wm = (warp & 3) * 32;
    const int wn = (warp >> 2) * 64;
    const int lrow = lane & 15;
    const int lcol = (lane >> 4) * 8;

    const uint32_t aA = smem_u32(sA), aB = smem_u32(sB);

    float acc[2][8][4];
#pragma unroll
    for (int i = 0; i < 2; i++)
#pragma unroll
        for (int n = 0; n < 8; n++)
#pragma unroll
            for (int q = 0; q < 4; q++) acc[i][n][q] = 0.f;

    const int srow = tid >> 2;
    const int skv = (tid & 3) * 8;

    for (int c = 0; c < nchunk; c++) {
        const int kb0 = c * 32;
#pragma unroll
        for (int jv = 0; jv < 2; jv++) {
            int row = srow + jv * 64;
            size_t go = (size_t)row * KPv + kb0 + skv;
            int so = row * AP + skv;
            *(uint4*)&sA[so] = *(const uint4*)(A + go);
            *(uint4*)&sB[so] = *(const uint4*)(B + go);
        }
        __syncthreads();
#pragma unroll
        for (int ks = 0; ks < 2; ks++) {
            const int kb = ks * 16;
            uint32_t ah[2][4];
#pragma unroll
            for (int i = 0; i < 2; i++) {
                uint32_t off = (uint32_t)(((wm + i * 16 + lrow) * AP + kb + lcol) * 2);
                ldsm_x4(aA + off, ah[i]);
            }
#pragma unroll
            for (int p = 0; p < 4; p++) {
                uint32_t off = (uint32_t)(((wn + p * 16 + lrow) * AP + kb + lcol) * 2);
                uint32_t bh[4];
                ldsm_x4(aB + off, bh);
#pragma unroll
                for (int i = 0; i < 2; i++) {
                    mma16816h(acc[i][2 * p],     ah[i], bh[0], bh[2]);
                    mma16816h(acc[i][2 * p + 1], ah[i], bh[1], bh[3]);
                }
            }
        }
        __syncthreads();
    }

    const float* b1 = dir ? bih_b : bih_f;
    const float* b2 = dir ? bhh_b : bhh_f;
    float* outp = (dir ? g_pre_b : g_pre_f) + ((size_t)t * 800 + m0) * NB;
#pragma unroll
    for (int i = 0; i < 2; i++) {
#pragma unroll
        for (int half = 0; half < 2; half++) {
            int ml = wm + i * 16 + half * 8 + (lane >> 2);
            if (m0 + ml < 800) {
                float bs = __ldg(&b1[m0 + ml]) + __ldg(&b2[m0 + ml]);
                float* op = outp + (size_t)ml * NB + wn + (lane & 3) * 2;
#pragma unroll
                for (int n = 0; n < 8; n++) {
                    float2 v = make_float2(acc[i][n][half * 2] + bs,
                                           acc[i][n][half * 2 + 1] + bs);
                    *(float2*)(op + n * 8) = v;
                }
            }
        }
    }
}

// ---------------- cluster recurrence: 32 CTAs = 8 clusters of 4 ----------------
// Cluster = (dir, bslice of 32 batch cols); ranks = 4 ugroups of 50 units.
// W resident in smem; h exchanged via DSMEM push + cluster barrier (no gmem!).
// smem: W [208][216] f16 @0 (89856) | hbuf 2x[32][216] f16 @89856 (27648) |
//       D [208][33] f32 @117504 (27456) | hsm [32][52] f16 @144960 (3328) = 148288
#define RS_H 89856
#define RS_D 117504
#define RS_HS 144960
#define RSMEM3 148288
__global__ __launch_bounds__(256) __cluster_dims__(4, 1, 1)
void k_recur_mma(int layer)
{
    extern __shared__ __align__(16) char dsm[];
    const uint32_t sb = smem_u32(dsm);
    const uint32_t sW = sb;
    const uint32_t sH = sb + RS_H;
    float* Dsm = (float*)(dsm + RS_D);
    __half* hsm = (__half*)(dsm + RS_HS);

    const int tid = threadIdx.x;
    const int warp = tid >> 5, lane = tid & 31;
    const int grp = blockIdx.x >> 2;       // 0..7
    const int ug = blockIdx.x & 3;         // cluster rank
    const int dir = grp >> 2;
    const int bs = grp & 3;
    const int b0 = bs * 32;
    const int lrow = lane & 15, lcol = (lane >> 4) * 8;

    const __half* wr = g_wr + ((size_t)(layer * 2 + dir) * 800 + (size_t)ug * 200) * KR;
    const float* pre = dir ? g_pre_b : g_pre_f;

    // stage resident W (200 rows x 208), zero pad rows 200..207, zero both h bufs
    for (int i = tid; i < 5200; i += 256) {
        int r = i / 26, seg = i - r * 26;
        cpasync16(sW + (uint32_t)((r * 216 + seg * 8) * 2), wr + (size_t)r * KR + seg * 8);
    }
    asm volatile("cp.async.commit_group;" ::: "memory");
    for (int i = tid; i < 864; i += 256)
        ((uint32_t*)(dsm + 200 * 216 * 2))[i] = 0u;
    for (int i = tid; i < 6912; i += 256)
        ((uint32_t*)(dsm + RS_H))[i] = 0u;
    asm volatile("cp.async.wait_group 0;" ::: "memory");
    __syncthreads();
    asm volatile("barrier.cluster.arrive.aligned;" ::: "memory");
    asm volatile("barrier.cluster.wait.aligned;" ::: "memory");

    float cc[7];
#pragma unroll
    for (int i = 0; i < 7; i++) cc[i] = 0.f;

    for (int s = 0; s < TT; s++) {
        const int t = dir ? (TT - 1 - s) : s;
        const uint32_t hcur = sH + (uint32_t)(s & 1) * 13824u;

        // pre-activations loaded directly as accumulator init
        float acc[2][4][4];
        const float* pt = pre + (size_t)t * 800 * NB + b0;
#pragma unroll
        for (int tt = 0; tt < 2; tt++) {
            int T = (tt == 0) ? warp : warp + 8;
            bool va = (tt == 0) || (warp < 5);
#pragma unroll
            for (int p = 0; p < 4; p++) {
                int c = p * 8 + (lane & 3) * 2;
#pragma unroll
                for (int hh = 0; hh < 2; hh++) {
                    int r = T * 16 + (lane >> 2) + hh * 8;
                    float2 v = make_float2(0.f, 0.f);
                    if (va && r < 200) {
                        int prow = (r & 3) * 200 + ug * 50 + (r >> 2);
                        v = *(const float2*)&pt[(size_t)prow * NB + c];
                    }
                    acc[tt][p][hh * 2] = v.x;
                    acc[tt][p][hh * 2 + 1] = v.y;
                }
            }
        }

        // MMA: D[208x32] = W @ h ; warp w handles M-tiles w and w+8 (w<5)
#pragma unroll
        for (int ko = 0; ko < 13; ko++) {
            uint32_t bf0[4], bf1[4];
            ldsm_x4(hcur + (uint32_t)((lrow * 216 + ko * 16 + lcol) * 2), bf0);
            ldsm_x4(hcur + (uint32_t)(((16 + lrow) * 216 + ko * 16 + lcol) * 2), bf1);
            {
                uint32_t a4[4];
                ldsm_x4(sW + (uint32_t)(((warp * 16 + lrow) * 216 + ko * 16 + lcol) * 2), a4);
                mma16816h(acc[0][0], a4, bf0[0], bf0[2]);
                mma16816h(acc[0][1], a4, bf0[1], bf0[3]);
                mma16816h(acc[0][2], a4, bf1[0], bf1[2]);
                mma16816h(acc[0][3], a4, bf1[1], bf1[3]);
            }
            if (warp < 5) {
                uint32_t a4[4];
                ldsm_x4(sW + (uint32_t)((((warp + 8) * 16 + lrow) * 216 + ko * 16 + lcol) * 2), a4);
                mma16816h(acc[1][0], a4, bf0[0], bf0[2]);
                mma16816h(acc[1][1], a4, bf0[1], bf0[3]);
                mma16816h(acc[1][2], a4, bf1[0], bf1[2]);
                mma16816h(acc[1][3], a4, bf1[1], bf1[3]);
            }
        }
        // D -> smem (stride 33)
#pragma unroll
        for (int tt = 0; tt < 2; tt++) {
            if (tt == 1 && warp >= 5) break;
            int T = (tt == 0) ? warp : warp + 8;
            int r = T * 16 + (lane >> 2);
#pragma unroll
            for (int p = 0; p < 4; p++) {
                int c = p * 8 + (lane & 3) * 2;
                Dsm[r * 33 + c] = acc[tt][p][0];
                Dsm[r * 33 + c + 1] = acc[tt][p][1];
                Dsm[(r + 8) * 33 + c] = acc[tt][p][2];
                Dsm[(r + 8) * 33 + c + 1] = acc[tt][p][3];
            }
        }
        __syncthreads();

        // gates: item i = (u_local, col); c-state per-thread registers
#pragma unroll
        for (int k = 0; k < 7; k++) {
            int i = tid + k * 256;
            if (i < 1600) {
                int ul = i >> 5, col = i & 31;
                float gi = Dsm[(ul * 4 + 0) * 33 + col];
                float gf = Dsm[(ul * 4 + 1) * 33 + col];
                float gg = Dsm[(ul * 4 + 2) * 33 + col];
                float go = Dsm[(ul * 4 + 3) * 33 + col];
                float cv = sigf(gf) * cc[k] + sigf(gi) * tanhfast(gg);
                cc[k] = cv;
                hsm[col * 52 + ul] = __float2half_rn(sigf(go) * tanhfast(cv));
            }
        }
        __syncthreads();

        // DSMEM push: my 50-unit slice -> all 4 cluster CTAs' next h buffer
        const uint32_t hnloc = sH + (uint32_t)((s + 1) & 1) * 13824u;
        for (int i = tid; i < 800; i += 256) {
            int col = i / 25, q = i - col * 25;
            uint32_t v = *(uint32_t*)&hsm[col * 52 + q * 2];
            uint32_t loc = hnloc + (uint32_t)((col * 216 + ug * 50 + q * 2) * 2);
#pragma unroll
            for (int rk = 0; rk < 4; rk++) {
                uint32_t pa;
                asm("mapa.shared::cluster.u32 %0, %1, %2;" : "=r"(pa) : "r"(loc), "r"(rk));
                asm volatile("st.shared::cluster.u32 [%0], %1;" :: "r"(pa), "r"(v) : "memory");
            }
        }
        asm volatile("barrier.cluster.arrive.aligned;" ::: "memory");

        // layer-output gmem stores overlap the barrier skew window
        for (int i = tid; i < 800; i += 256) {
            int col = i / 25, q = i - col * 25;
            uint32_t v = *(uint32_t*)&hsm[col * 52 + q * 2];
            if (layer == 0) {
                size_t o = ((size_t)t * NB + b0 + col) * KP1 + dir * 200 + ug * 50 + q * 2;
                *(uint32_t*)&g_h0[o] = v;
            } else {
                size_t o = ((size_t)(b0 + col) * TT + t) * 416 + dir * 200 + ug * 50 + q * 2;
                *(uint32_t*)&g_hbt[o] = v;
            }
        }
        asm volatile("barrier.cluster.wait.aligned;" ::: "memory");
    }
}

// ---------------- tensor-core path-gather + MLP1 (tanh), fp16 single ----------------
__global__ __launch_bounds__(256) void k_gather_mma(
    const int* __restrict__ paths, const float* __restrict__ b1)
{
    __shared__ __align__(16) __half sA[128 * AP];
    __shared__ __align__(16) __half sB[128 * AP];
    __shared__ long long abase[128][2];

    const int tid = threadIdx.x;
    const int warp = tid >> 5, lane = tid & 31;
    const int s0 = blockIdx.x * 128;
    const int n0 = blockIdx.y * 128;

    {
        int i = tid >> 1, j = tid & 1;
        int s = s0 + i;
        int tval = paths[(size_t)s * 2 + j];
        int b = s >> 8;
        abase[i][j] = (tval >= 0) ? ((long long)b * TT + tval) * 416LL : -1LL;
    }
    __syncthreads();

    const int wm = (warp & 3) * 32;
    const int wn = (warp >> 2) * 64;
    const int lrow = lane & 15;
    const int lcol = (lane >> 4) * 8;

    const uint32_t aA = smem_u32(sA), aB = smem_u32(sB);

    float acc[2][8][4];
#pragma unroll
    for (int i = 0; i < 2; i++)
#pragma unroll
        for (int n = 0; n < 8; n++)
#pragma unroll
            for (int q = 0; q < 4; q++) acc[i][n][q] = 0.f;

    const int srow = tid >> 2;
    const int skv = (tid & 3) * 8;

    for (int c = 0; c < 26; c++) {
        const int j = (c >= 13) ? 1 : 0;
        const int kloc = c * 32 - j * 416 + skv;
        const int kb0 = c * 32;
#pragma unroll
        for (int jv = 0; jv < 2; jv++) {
            int row = srow + jv * 64;
            int so = row * AP + skv;
            long long ab = abase[row][j];
            uint4 vh = make_uint4(0u, 0u, 0u, 0u);
            if (ab >= 0) vh = *(const uint4*)(g_hbt + ab + kloc);
            *(uint4*)&sA[so] = vh;
            *(uint4*)&sB[so] = *(const uint4*)(g_w1p + (size_t)(n0 + row) * KG + kb0 + skv);
        }
        __syncthreads();
#pragma unroll
        for (int ks = 0; ks < 2; ks++) {
            const int kb = ks * 16;
            uint32_t ah[2][4];
#pragma unroll
            for (int i = 0; i < 2; i++) {
                uint32_t off = (uint32_t)(((wm + i * 16 + lrow) * AP + kb + lcol) * 2);
                ldsm_x4(aA + off, ah[i]);
            }
#pragma unroll
            for (int p = 0; p < 4; p++) {
                uint32_t off = (uint32_t)(((wn + p * 16 + lrow) * AP + kb + lcol) * 2);
                uint32_t bh[4];
                ldsm_x4(aB + off, bh);
#pragma unroll
                for (int i = 0; i < 2; i++) {
                    mma16816h(acc[i][2 * p],     ah[i], bh[0], bh[2]);
                    mma16816h(acc[i][2 * p + 1], ah[i], bh[1], bh[3]);
                }
            }
        }
        __syncthreads();
    }

#pragma unroll
    for (int i = 0; i < 2; i++) {
#pragma unroll
        for (int half = 0; half < 2; half++) {
            int ml = wm + i * 16 + half * 8 + (lane >> 2);
            int s = s0 + ml;
#pragma unroll
            for (int n = 0; n < 8; n++) {
                int nn = n0 + wn + (lane & 3) * 2 + n * 8;
                if (nn < 200) {
                    float2 v = make_float2(
                        tanhf(acc[i][n][half * 2] + __ldg(&b1[nn])),
                        tanhf(acc[i][n][half * 2 + 1] + __ldg(&b1[nn + 1])));
                    *(float2*)&g_hid[(size_t)s * 200 + nn] = v;
                }
            }
        }
    }
}

// ---------------- MLP2 + softmax: one warp per sample ----------------
__global__ __launch_bounds__(128) void k_mlp2(
    const float* __restrict__ w2, const float* __restrict__ b2, float* __restrict__ out)
{
    __shared__ float w2s[800];
    __shared__ float b2s[4];
    const int tid = threadIdx.x;
    for (int i = tid; i < 800; i += 128) w2s[i] = w2[i];
    if (tid < 4) b2s[tid] = b2[tid];
    __syncthreads();
    const int warp = tid >> 5, lane = tid & 31;
    const int s = blockIdx.x * 4 + warp;
    const float* hr = g_hid + (size_t)s * 200;
    float a0 = 0.f, a1 = 0.f, a2 = 0.f, a3 = 0.f;
    for (int k = lane; k < 200; k += 32) {
        float h = hr[k];
        a0 += h * w2s[k];
        a1 += h * w2s[200 + k];
        a2 += h * w2s[400 + k];
        a3 += h * w2s[600 + k];
    }
#pragma unroll
    for (int o = 16; o > 0; o >>= 1) {
        a0 += __shfl_down_sync(0xffffffffu, a0, o);
        a1 += __shfl_down_sync(0xffffffffu, a1, o);
        a2 += __shfl_down_sync(0xffffffffu, a2, o);
        a3 += __shfl_down_sync(0xffffffffu, a3, o);
    }
    if (lane == 0) {
        float l0 = a0 + b2s[0], l1 = a1 + b2s[1], l2 = a2 + b2s[2], l3 = a3 + b2s[3];
        float m = fmaxf(fmaxf(l0, l1), fmaxf(l2, l3));
        float e0 = expf(l0 - m), e1 = expf(l1 - m), e2 = expf(l2 - m), e3 = expf(l3 - m);
        float inv = 1.f / (e0 + e1 + e2 + e3);
        float4 r = make_float4(e0 * inv, e1 * inv, e2 * inv, e3 * inv);
        *(float4*)&out[(size_t)s * 4] = r;
    }
}

extern "C" void kernel_launch(void* const* d_in, const int* in_sizes, int n_in,
                              void* d_out, int out_size)
{
    const int* tokens = (const int*)d_in[0];
    const int* paths = (const int*)d_in[1];
    const float* emb = (const float*)d_in[2];
    const float* wih0f = (const float*)d_in[3];
    const float* whh0f = (const float*)d_in[4];
    const float* bih0f = (const float*)d_in[5];
    const float* bhh0f = (const float*)d_in[6];
    const float* wih0b = (const float*)d_in[7];
    const float* whh0b = (const float*)d_in[8];
    const float* bih0b = (const float*)d_in[9];
    const float* bhh0b = (const float*)d_in[10];
    const float* wih1f = (const float*)d_in[11];
    const float* whh1f = (const float*)d_in[12];
    const float* bih1f = (const float*)d_in[13];
    const float* bhh1f = (const float*)d_in[14];
    const float* wih1b = (const float*)d_in[15];
    const float* whh1b = (const float*)d_in[16];
    const float* bih1b = (const float*)d_in[17];
    const float* bhh1b = (const float*)d_in[18];
    const float* w1 = (const float*)d_in[19];
    const float* b1 = (const float*)d_in[20];
    const float* w2 = (const float*)d_in[21];
    const float* b2 = (const float*)d_in[22];
    float* out = (float*)d_out;

    cudaFuncSetAttribute(k_recur_mma, cudaFuncAttributeMaxDynamicSharedMemorySize, RSMEM3);

    k_embsplit<<<TT, 256>>>(tokens, emb);                               // launch 1
    dim3 gw((896 * KP1 + 255) / 256, 9);
    k_prepw<<<gw, 256>>>(wih0f, wih0b, wih1f, wih1b,
                         whh0f, whh0b, whh1f, whh1b, w1);               // launch 2

    dim3 gg(7, TT, 2);
    k_gemm_mma<<<gg, 256>>>(0, bih0f, bhh0f, bih0b, bhh0b);             // launch 3
    k_recur_mma<<<32, 256, RSMEM3>>>(0);                                // launch 4 (profiled)
    k_gemm_mma<<<gg, 256>>>(1, bih1f, bhh1f, bih1b, bhh1b);             // launch 5
    k_recur_mma<<<32, 256, RSMEM3>>>(1);                                // launch 6

    dim3 g4(NSAMP / 128, 2);
    k_gather_mma<<<g4, 256>>>(paths, b1);                               // launch 7
    k_mlp2<<<NSAMP / 4, 128>>>(w2, b2, out);                            // launch 8
}

// round 15
// speedup vs baseline: 1.9757x; 1.2669x over previous
#include <cuda_runtime.h>
#include <cuda_fp16.h>
#include <cstdint>

#define TT 512
#define NB 128
#define NSAMP 32768
#define KP0 224
#define KP1 416
#define AP 40    // GEMM smem stride (elems) for 32-wide k chunks
#define KR 208   // recurrence padded K (13 x k16)
#define KG 832   // gather-MLP padded K (2 x 416)

// ---------------- static scratch (no allocation; zero-initialized at load) -------
__device__ float g_pre_f[(size_t)TT * 800 * NB];   // (t, gate, b)
__device__ float g_pre_b[(size_t)TT * 800 * NB];
__device__ float g_hid[(size_t)NSAMP * 200];       // MLP hidden (s, n)

// fp16 single-precision operand buffers (error model calibrated round 10)
__device__ __align__(16) __half g_w0[(size_t)2 * 896 * KP0];  // [dir][m][k]
__device__ __align__(16) __half g_w1[(size_t)2 * 896 * KP1];
__device__ __align__(16) __half g_x[(size_t)TT * NB * KP0];   // (t, b, k)
__device__ __align__(16) __half g_h0[(size_t)TT * NB * KP1];  // layer0 out (t,b,k)
// layer1 out, (b, t, u) padded to 416; pad region [400,416) stays zero forever
__device__ __align__(16) __half g_hbt[(size_t)NB * TT * 416];
// w1 padded: [256 rows][KG]
__device__ __align__(16) __half g_w1p[(size_t)256 * KG];
// recurrence weights, interleaved rows (u*4+g), [layer][dir][800][KR]
__device__ __align__(16) __half g_wr[(size_t)2 * 2 * 800 * KR];

// ---------------- helpers ----------------
__device__ __forceinline__ float tanhapx(float x) {
    float y;
    asm("tanh.approx.f32 %0, %1;" : "=f"(y) : "f"(x));
    return y;
}
__device__ __forceinline__ float sigapx(float x) {
    return fmaf(0.5f, tanhapx(0.5f * x), 0.5f);
}
__device__ __forceinline__ uint32_t smem_u32(const void* p) {
    uint32_t a;
    asm("{ .reg .u64 t; cvta.to.shared.u64 t, %1; cvt.u32.u64 %0, t; }" : "=r"(a) : "l"(p));
    return a;
}
__device__ __forceinline__ void ldsm_x4(uint32_t addr, uint32_t r[4]) {
    asm volatile("ldmatrix.sync.aligned.m8n8.x4.shared.b16 {%0,%1,%2,%3}, [%4];"
        : "=r"(r[0]), "=r"(r[1]), "=r"(r[2]), "=r"(r[3]) : "r"(addr));
}
__device__ __forceinline__ void mma16816h(float d[4], const uint32_t a[4],
                                          uint32_t b0, uint32_t b1) {
    asm volatile(
        "mma.sync.aligned.m16n8k16.row.col.f32.f16.f16.f32 "
        "{%0,%1,%2,%3}, {%4,%5,%6,%7}, {%8,%9}, {%0,%1,%2,%3};"
        : "+f"(d[0]), "+f"(d[1]), "+f"(d[2]), "+f"(d[3])
        : "r"(a[0]), "r"(a[1]), "r"(a[2]), "r"(a[3]), "r"(b0), "r"(b1));
}
__device__ __forceinline__ void cpasync16(uint32_t dst, const void* src) {
    asm volatile("cp.async.cg.shared.global [%0], [%1], 16;" :: "r"(dst), "l"(src));
}

// ---------------- embedding -> fp16, (t, b, k) padded to KP0 ----------------
__global__ __launch_bounds__(256) void k_embsplit(const int* __restrict__ tokens,
                                                  const float* __restrict__ emb) {
    int t = blockIdx.x;
    __shared__ int stok[NB];
    if (threadIdx.x < NB) stok[threadIdx.x] = tokens[t * NB + threadIdx.x];
    __syncthreads();
    size_t base = (size_t)t * NB * KP0;
    for (int idx = threadIdx.x; idx < NB * KP0; idx += 256) {
        int b = idx / KP0, k = idx - b * KP0;
        float v = (k < 200) ? __ldg(&emb[(size_t)stok[b] * 200 + k]) : 0.f;
        g_x[base + idx] = __float2half_rn(v);
    }
}

// ---------------- ALL weight prep (fp16 single) ----------------
__global__ __launch_bounds__(256) void k_prepw(
    const float* __restrict__ w0f, const float* __restrict__ w0b,
    const float* __restrict__ w1f, const float* __restrict__ w1b,
    const float* __restrict__ r0f, const float* __restrict__ r0b,
    const float* __restrict__ r1f, const float* __restrict__ r1b,
    const float* __restrict__ w1)
{
    int sel = blockIdx.y;
    int idx = blockIdx.x * 256 + threadIdx.x;
    if (sel < 4) {
        int layer = sel >> 1, dirv = sel & 1;
        const float* w = (sel == 0) ? w0f : (sel == 1) ? w0b : (sel == 2) ? w1f : w1b;
        int K = layer ? 400 : 200;
        int KPv = layer ? KP1 : KP0;
        if (idx >= 896 * KPv) return;
        __half* d = (layer ? g_w1 : g_w0) + (size_t)dirv * 896 * KPv;
        int m = idx / KPv, k = idx - m * KPv;
        float v = (m < 800 && k < K) ? __ldg(&w[(size_t)m * K + k]) : 0.f;
        d[idx] = __float2half_rn(v);
    } else if (sel < 8) {
        int layer = (sel - 4) >> 1, dirv = (sel - 4) & 1;
        const float* w = (sel == 4) ? r0f : (sel == 5) ? r0b : (sel == 6) ? r1f : r1b;
        if (idx >= 800 * KR) return;
        int r = idx / KR, k = idx - r * KR;
        int u = r >> 2, g = r & 3;
        float v = (k < 200) ? __ldg(&w[(size_t)(g * 200 + u) * 200 + k]) : 0.f;
        g_wr[((size_t)(layer * 2 + dirv) * 800 + r) * KR + k] = __float2half_rn(v);
    } else {
        if (idx >= 256 * KG) return;
        int n = idx / KG, kk = idx - n * KG;
        float v = 0.f;
        if (n < 200) {
            if (kk < 400) v = __ldg(&w1[(size_t)n * 800 + kk]);
            else if (kk >= 416 && kk < 816) v = __ldg(&w1[(size_t)n * 800 + kk - 16]);
        }
        g_w1p[idx] = __float2half_rn(v);
    }
}

// ---------------- tensor-core pre-GEMM (fp16 single) ----------------
__global__ __launch_bounds__(256) void k_gemm_mma(
    int layer,
    const float* __restrict__ bih_f, const float* __restrict__ bhh_f,
    const float* __restrict__ bih_b, const float* __restrict__ bhh_b)
{
    __shared__ __align__(16) __half sA[128 * AP];
    __shared__ __align__(16) __half sB[128 * AP];

    const int tid = threadIdx.x;
    const int warp = tid >> 5, lane = tid & 31;
    const int m0 = blockIdx.x * 128;
    const int t = blockIdx.y;
    const int dir = blockIdx.z;
    const int KPv = layer ? KP1 : KP0;
    const int nchunk = KPv >> 5;
    const __half* A = (layer ? g_w1 : g_w0) + (size_t)dir * 896 * KPv + (size_t)m0 * KPv;
    const __half* B = (layer ? g_h0 : g_x) + (size_t)t * NB * KPv;

    const int wm = (warp & 3) * 32;
    const int wn = (warp >> 2) * 64;
    const int lrow = lane & 15;
    const int lcol = (lane >> 4) * 8;

    const uint32_t aA = smem_u32(sA), aB = smem_u32(sB);

    float acc[2][8][4];
#pragma unroll
    for (int i = 0; i < 2; i++)
#pragma unroll
        for (int n = 0; n < 8; n++)
#pragma unroll
            for (int q = 0; q < 4; q++) acc[i][n][q] = 0.f;

    const int srow = tid >> 2;
    const int skv = (tid & 3) * 8;

    for (int c = 0; c < nchunk; c++) {
        const int kb0 = c * 32;
#pragma unroll
        for (int jv = 0; jv < 2; jv++) {
            int row = srow + jv * 64;
            size_t go = (size_t)row * KPv + kb0 + skv;
            int so = row * AP + skv;
            *(uint4*)&sA[so] = *(const uint4*)(A + go);
            *(uint4*)&sB[so] = *(const uint4*)(B + go);
        }
        __syncthreads();
#pragma unroll
        for (int ks = 0; ks < 2; ks++) {
            const int kb = ks * 16;
            uint32_t ah[2][4];
#pragma unroll
            for (int i = 0; i < 2; i++) {
                uint32_t off = (uint32_t)(((wm + i * 16 + lrow) * AP + kb + lcol) * 2);
                ldsm_x4(aA + off, ah[i]);
            }
#pragma unroll
            for (int p = 0; p < 4; p++) {
                uint32_t off = (uint32_t)(((wn + p * 16 + lrow) * AP + kb + lcol) * 2);
                uint32_t bh[4];
                ldsm_x4(aB + off, bh);
#pragma unroll
                for (int i = 0; i < 2; i++) {
                    mma16816h(acc[i][2 * p],     ah[i], bh[0], bh[2]);
                    mma16816h(acc[i][2 * p + 1], ah[i], bh[1], bh[3]);
                }
            }
        }
        __syncthreads();
    }

    const float* b1 = dir ? bih_b : bih_f;
    const float* b2 = dir ? bhh_b : bhh_f;
    float* outp = (dir ? g_pre_b : g_pre_f) + ((size_t)t * 800 + m0) * NB;
#pragma unroll
    for (int i = 0; i < 2; i++) {
#pragma unroll
        for (int half = 0; half < 2; half++) {
            int ml = wm + i * 16 + half * 8 + (lane >> 2);
            if (m0 + ml < 800) {
                float bs = __ldg(&b1[m0 + ml]) + __ldg(&b2[m0 + ml]);
                float* op = outp + (size_t)ml * NB + wn + (lane & 3) * 2;
#pragma unroll
                for (int n = 0; n < 8; n++) {
                    float2 v = make_float2(acc[i][n][half * 2] + bs,
                                           acc[i][n][half * 2 + 1] + bs);
                    *(float2*)(op + n * 8) = v;
                }
            }
        }
    }
}

// ---------------- cluster recurrence: 32 CTAs = 8 clusters of 4 ----------------
// Cluster = (dir, bslice of 32 batch cols); ranks = 4 ugroups of 50 units.
// W resident in smem; h exchanged via DSMEM push + cluster barrier (no gmem!).
// Gate nonlinearities via HW tanh.approx (1 MUFU each).
// smem: W [208][216] f16 @0 (89856) | hbuf 2x[32][216] f16 @89856 (27648) |
//       D [208][33] f32 @117504 (27456) | hsm [32][52] f16 @144960 (3328) = 148288
#define RS_H 89856
#define RS_D 117504
#define RS_HS 144960
#define RSMEM3 148288
__global__ __launch_bounds__(256) __cluster_dims__(4, 1, 1)
void k_recur_mma(int layer)
{
    extern __shared__ __align__(16) char dsm[];
    const uint32_t sb = smem_u32(dsm);
    const uint32_t sW = sb;
    const uint32_t sH = sb + RS_H;
    float* Dsm = (float*)(dsm + RS_D);
    __half* hsm = (__half*)(dsm + RS_HS);

    const int tid = threadIdx.x;
    const int warp = tid >> 5, lane = tid & 31;
    const int grp = blockIdx.x >> 2;       // 0..7
    const int ug = blockIdx.x & 3;         // cluster rank
    const int dir = grp >> 2;
    const int bs = grp & 3;
    const int b0 = bs * 32;
    const int lrow = lane & 15, lcol = (lane >> 4) * 8;

    const __half* wr = g_wr + ((size_t)(layer * 2 + dir) * 800 + (size_t)ug * 200) * KR;
    const float* pre = dir ? g_pre_b : g_pre_f;

    // stage resident W (200 rows x 208), zero pad rows 200..207, zero both h bufs
    for (int i = tid; i < 5200; i += 256) {
        int r = i / 26, seg = i - r * 26;
        cpasync16(sW + (uint32_t)((r * 216 + seg * 8) * 2), wr + (size_t)r * KR + seg * 8);
    }
    asm volatile("cp.async.commit_group;" ::: "memory");
    for (int i = tid; i < 864; i += 256)
        ((uint32_t*)(dsm + 200 * 216 * 2))[i] = 0u;
    for (int i = tid; i < 6912; i += 256)
        ((uint32_t*)(dsm + RS_H))[i] = 0u;
    asm volatile("cp.async.wait_group 0;" ::: "memory");
    __syncthreads();
    asm volatile("barrier.cluster.arrive.aligned;" ::: "memory");
    asm volatile("barrier.cluster.wait.aligned;" ::: "memory");

    float cc[7];
#pragma unroll
    for (int i = 0; i < 7; i++) cc[i] = 0.f;

    for (int s = 0; s < TT; s++) {
        const int t = dir ? (TT - 1 - s) : s;
        const uint32_t hcur = sH + (uint32_t)(s & 1) * 13824u;

        // pre-activations loaded directly as accumulator init
        float acc[2][4][4];
        const float* pt = pre + (size_t)t * 800 * NB + b0;
#pragma unroll
        for (int tt = 0; tt < 2; tt++) {
            int T = (tt == 0) ? warp : warp + 8;
            bool va = (tt == 0) || (warp < 5);
#pragma unroll
            for (int p = 0; p < 4; p++) {
                int c = p * 8 + (lane & 3) * 2;
#pragma unroll
                for (int hh = 0; hh < 2; hh++) {
                    int r = T * 16 + (lane >> 2) + hh * 8;
                    float2 v = make_float2(0.f, 0.f);
                    if (va && r < 200) {
                        int prow = (r & 3) * 200 + ug * 50 + (r >> 2);
                        v = *(const float2*)&pt[(size_t)prow * NB + c];
                    }
                    acc[tt][p][hh * 2] = v.x;
                    acc[tt][p][hh * 2 + 1] = v.y;
                }
            }
        }

        // MMA: D[208x32] = W @ h ; warp w handles M-tiles w and w+8 (w<5)
#pragma unroll
        for (int ko = 0; ko < 13; ko++) {
            uint32_t bf0[4], bf1[4];
            ldsm_x4(hcur + (uint32_t)((lrow * 216 + ko * 16 + lcol) * 2), bf0);
            ldsm_x4(hcur + (uint32_t)(((16 + lrow) * 216 + ko * 16 + lcol) * 2), bf1);
            {
                uint32_t a4[4];
                ldsm_x4(sW + (uint32_t)(((warp * 16 + lrow) * 216 + ko * 16 + lcol) * 2), a4);
                mma16816h(acc[0][0], a4, bf0[0], bf0[2]);
                mma16816h(acc[0][1], a4, bf0[1], bf0[3]);
                mma16816h(acc[0][2], a4, bf1[0], bf1[2]);
                mma16816h(acc[0][3], a4, bf1[1], bf1[3]);
            }
            if (warp < 5) {
                uint32_t a4[4];
                ldsm_x4(sW + (uint32_t)((((warp + 8) * 16 + lrow) * 216 + ko * 16 + lcol) * 2), a4);
                mma16816h(acc[1][0], a4, bf0[0], bf0[2]);
                mma16816h(acc[1][1], a4, bf0[1], bf0[3]);
                mma16816h(acc[1][2], a4, bf1[0], bf1[2]);
                mma16816h(acc[1][3], a4, bf1[1], bf1[3]);
            }
        }
        // D -> smem (stride 33)
#pragma unroll
        for (int tt = 0; tt < 2; tt++) {
            if (tt == 1 && warp >= 5) break;
            int T = (tt == 0) ? warp : warp + 8;
            int r = T * 16 + (lane >> 2);
#pragma unroll
            for (int p = 0; p < 4; p++) {
                int c = p * 8 + (lane & 3) * 2;
                Dsm[r * 33 + c] = acc[tt][p][0];
                Dsm[r * 33 + c + 1] = acc[tt][p][1];
                Dsm[(r + 8) * 33 + c] = acc[tt][p][2];
                Dsm[(r + 8) * 33 + c + 1] = acc[tt][p][3];
            }
        }
        __syncthreads();

        // gates: item i = (u_local, col); HW tanh.approx (5 MUFU/item)
#pragma unroll
        for (int k = 0; k < 7; k++) {
            int i = tid + k * 256;
            if (i < 1600) {
                int ul = i >> 5, col = i & 31;
                float gi = Dsm[(ul * 4 + 0) * 33 + col];
                float gf = Dsm[(ul * 4 + 1) * 33 + col];
                float gg = Dsm[(ul * 4 + 2) * 33 + col];
                float go = Dsm[(ul * 4 + 3) * 33 + col];
                float cv = sigapx(gf) * cc[k] + sigapx(gi) * tanhapx(gg);
                cc[k] = cv;
                hsm[col * 52 + ul] = __float2half_rn(sigapx(go) * tanhapx(cv));
            }
        }
        __syncthreads();

        // DSMEM push: my 50-unit slice -> all 4 cluster CTAs' next h buffer
        const uint32_t hnloc = sH + (uint32_t)((s + 1) & 1) * 13824u;
        for (int i = tid; i < 800; i += 256) {
            int col = i / 25, q = i - col * 25;
            uint32_t v = *(uint32_t*)&hsm[col * 52 + q * 2];
            uint32_t loc = hnloc + (uint32_t)((col * 216 + ug * 50 + q * 2) * 2);
#pragma unroll
            for (int rk = 0; rk < 4; rk++) {
                uint32_t pa;
                asm("mapa.shared::cluster.u32 %0, %1, %2;" : "=r"(pa) : "r"(loc), "r"(rk));
                asm volatile("st.shared::cluster.u32 [%0], %1;" :: "r"(pa), "r"(v) : "memory");
            }
        }
        asm volatile("barrier.cluster.arrive.aligned;" ::: "memory");

        // layer-output gmem stores overlap the barrier skew window
        for (int i = tid; i < 800; i += 256) {
            int col = i / 25, q = i - col * 25;
            uint32_t v = *(uint32_t*)&hsm[col * 52 + q * 2];
            if (layer == 0) {
                size_t o = ((size_t)t * NB + b0 + col) * KP1 + dir * 200 + ug * 50 + q * 2;
                *(uint32_t*)&g_h0[o] = v;
            } else {
                size_t o = ((size_t)(b0 + col) * TT + t) * 416 + dir * 200 + ug * 50 + q * 2;
                *(uint32_t*)&g_hbt[o] = v;
            }
        }
        asm volatile("barrier.cluster.wait.aligned;" ::: "memory");
    }
}

// ---------------- tensor-core path-gather + MLP1 (tanh), fp16 single ----------------
__global__ __launch_bounds__(256) void k_gather_mma(
    const int* __restrict__ paths, const float* __restrict__ b1)
{
    __shared__ __align__(16) __half sA[128 * AP];
    __shared__ __align__(16) __half sB[128 * AP];
    __shared__ long long abase[128][2];

    const int tid = threadIdx.x;
    const int warp = tid >> 5, lane = tid & 31;
    const int s0 = blockIdx.x * 128;
    const int n0 = blockIdx.y * 128;

    {
        int i = tid >> 1, j = tid & 1;
        int s = s0 + i;
        int tval = paths[(size_t)s * 2 + j];
        int b = s >> 8;
        abase[i][j] = (tval >= 0) ? ((long long)b * TT + tval) * 416LL : -1LL;
    }
    __syncthreads();

    const int wm = (warp & 3) * 32;
    const int wn = (warp >> 2) * 64;
    const int lrow = lane & 15;
    const int lcol = (lane >> 4) * 8;

    const uint32_t aA = smem_u32(sA), aB = smem_u32(sB);

    float acc[2][8][4];
#pragma unroll
    for (int i = 0; i < 2; i++)
#pragma unroll
        for (int n = 0; n < 8; n++)
#pragma unroll
            for (int q = 0; q < 4; q++) acc[i][n][q] = 0.f;

    const int srow = tid >> 2;
    const int skv = (tid & 3) * 8;

    for (int c = 0; c < 26; c++) {
        const int j = (c >= 13) ? 1 : 0;
        const int kloc = c * 32 - j * 416 + skv;
        const int kb0 = c * 32;
#pragma unroll
        for (int jv = 0; jv < 2; jv++) {
            int row = srow + jv * 64;
            int so = row * AP + skv;
            long long ab = abase[row][j];
            uint4 vh = make_uint4(0u, 0u, 0u, 0u);
            if (ab >= 0) vh = *(const uint4*)(g_hbt + ab + kloc);
            *(uint4*)&sA[so] = vh;
            *(uint4*)&sB[so] = *(const uint4*)(g_w1p + (size_t)(n0 + row) * KG + kb0 + skv);
        }
        __syncthreads();
#pragma unroll
        for (int ks = 0; ks < 2; ks++) {
            const int kb = ks * 16;
            uint32_t ah[2][4];
#pragma unroll
            for (int i = 0; i < 2; i++) {
                uint32_t off = (uint32_t)(((wm + i * 16 + lrow) * AP + kb + lcol) * 2);
                ldsm_x4(aA + off, ah[i]);
            }
#pragma unroll
            for (int p = 0; p < 4; p++) {
                uint32_t off = (uint32_t)(((wn + p * 16 + lrow) * AP + kb + lcol) * 2);
                uint32_t bh[4];
                ldsm_x4(aB + off, bh);
#pragma unroll
                for (int i = 0; i < 2; i++) {
                    mma16816h(acc[i][2 * p],     ah[i], bh[0], bh[2]);
                    mma16816h(acc[i][2 * p + 1], ah[i], bh[1], bh[3]);
                }
            }
        }
        __syncthreads();
    }

#pragma unroll
    for (int i = 0; i < 2; i++) {
#pragma unroll
        for (int half = 0; half < 2; half++) {
            int ml = wm + i * 16 + half * 8 + (lane >> 2);
            int s = s0 + ml;
#pragma unroll
            for (int n = 0; n < 8; n++) {
                int nn = n0 + wn + (lane & 3) * 2 + n * 8;
                if (nn < 200) {
                    float2 v = make_float2(
                        tanhapx(acc[i][n][half * 2] + __ldg(&b1[nn])),
                        tanhapx(acc[i][n][half * 2 + 1] + __ldg(&b1[nn + 1])));
                    *(float2*)&g_hid[(size_t)s * 200 + nn] = v;
                }
            }
        }
    }
}

// ---------------- MLP2 + softmax: one warp per sample ----------------
__global__ __launch_bounds__(128) void k_mlp2(
    const float* __restrict__ w2, const float* __restrict__ b2, float* __restrict__ out)
{
    __shared__ float w2s[800];
    __shared__ float b2s[4];
    const int tid = threadIdx.x;
    for (int i = tid; i < 800; i += 128) w2s[i] = w2[i];
    if (tid < 4) b2s[tid] = b2[tid];
    __syncthreads();
    const int warp = tid >> 5, lane = tid & 31;
    const int s = blockIdx.x * 4 + warp;
    const float* hr = g_hid + (size_t)s * 200;
    float a0 = 0.f, a1 = 0.f, a2 = 0.f, a3 = 0.f;
    for (int k = lane; k < 200; k += 32) {
        float h = hr[k];
        a0 += h * w2s[k];
        a1 += h * w2s[200 + k];
        a2 += h * w2s[400 + k];
        a3 += h * w2s[600 + k];
    }
#pragma unroll
    for (int o = 16; o > 0; o >>= 1) {
        a0 += __shfl_down_sync(0xffffffffu, a0, o);
        a1 += __shfl_down_sync(0xffffffffu, a1, o);
        a2 += __shfl_down_sync(0xffffffffu, a2, o);
        a3 += __shfl_down_sync(0xffffffffu, a3, o);
    }
    if (lane == 0) {
        float l0 = a0 + b2s[0], l1 = a1 + b2s[1], l2 = a2 + b2s[2], l3 = a3 + b2s[3];
        float m = fmaxf(fmaxf(l0, l1), fmaxf(l2, l3));
        float e0 = expf(l0 - m), e1 = expf(l1 - m), e2 = expf(l2 - m), e3 = expf(l3 - m);
        float inv = 1.f / (e0 + e1 + e2 + e3);
        float4 r = make_float4(e0 * inv, e1 * inv, e2 * inv, e3 * inv);
        *(float4*)&out[(size_t)s * 4] = r;
    }
}

extern "C" void kernel_launch(void* const* d_in, const int* in_sizes, int n_in,
                              void* d_out, int out_size)
{
    const int* tokens = (const int*)d_in[0];
    const int* paths = (const int*)d_in[1];
    const float* emb = (const float*)d_in[2];
    const float* wih0f = (const float*)d_in[3];
    const float* whh0f = (const float*)d_in[4];
    const float* bih0f = (const float*)d_in[5];
    const float* bhh0f = (const float*)d_in[6];
    const float* wih0b = (const float*)d_in[7];
    const float* whh0b = (const float*)d_in[8];
    const float* bih0b = (const float*)d_in[9];
    const float* bhh0b = (const float*)d_in[10];
    const float* wih1f = (const float*)d_in[11];
    const float* whh1f = (const float*)d_in[12];
    const float* bih1f = (const float*)d_in[13];
    const float* bhh1f = (const float*)d_in[14];
    const float* wih1b = (const float*)d_in[15];
    const float* whh1b = (const float*)d_in[16];
    const float* bih1b = (const float*)d_in[17];
    const float* bhh1b = (const float*)d_in[18];
    const float* w1 = (const float*)d_in[19];
    const float* b1 = (const float*)d_in[20];
    const float* w2 = (const float*)d_in[21];
    const float* b2 = (const float*)d_in[22];
    float* out = (float*)d_out;

    cudaFuncSetAttribute(k_recur_mma, cudaFuncAttributeMaxDynamicSharedMemorySize, RSMEM3);

    k_embsplit<<<TT, 256>>>(tokens, emb);                               // launch 1
    dim3 gw((896 * KP1 + 255) / 256, 9);
    k_prepw<<<gw, 256>>>(wih0f, wih0b, wih1f, wih1b,
                         whh0f, whh0b, whh1f, whh1b, w1);               // launch 2

    dim3 gg(7, TT, 2);
    k_gemm_mma<<<gg, 256>>>(0, bih0f, bhh0f, bih0b, bhh0b);             // launch 3
    k_recur_mma<<<32, 256, RSMEM3>>>(0);                                // launch 4 (profiled)
    k_gemm_mma<<<gg, 256>>>(1, bih1f, bhh1f, bih1b, bhh1b);             // launch 5
    k_recur_mma<<<32, 256, RSMEM3>>>(1);                                // launch 6

    dim3 g4(NSAMP / 128, 2);
    k_gather_mma<<<g4, 256>>>(paths, b1);                               // launch 7
    k_mlp2<<<NSAMP / 4, 128>>>(w2, b2, out);                            // launch 8
}

// round 16
// speedup vs baseline: 2.4274x; 1.2287x over previous
#include <cuda_runtime.h>
#include <cuda_fp16.h>
#include <cstdint>

#define TT 512
#define NB 128
#define NSAMP 32768
#define KP0 224
#define KP1 416
#define AP 40    // GEMM smem stride (elems) for 32-wide k chunks
#define KR 208   // recurrence padded K (13 x k16)
#define KG 832   // gather-MLP padded K (2 x 416)

// ---------------- static scratch (no allocation; zero-initialized at load) -------
__device__ float g_pre_f[(size_t)TT * 800 * NB];   // (t, gate, b)
__device__ float g_pre_b[(size_t)TT * 800 * NB];
__device__ float g_hid[(size_t)NSAMP * 200];       // MLP hidden (s, n)

// fp16 single-precision operand buffers (error model calibrated round 10)
__device__ __align__(16) __half g_w0[(size_t)2 * 896 * KP0];  // [dir][m][k]
__device__ __align__(16) __half g_w1[(size_t)2 * 896 * KP1];
__device__ __align__(16) __half g_x[(size_t)TT * NB * KP0];   // (t, b, k)
__device__ __align__(16) __half g_h0[(size_t)TT * NB * KP1];  // layer0 out (t,b,k)
// layer1 out, (b, t, u) padded to 416; pad region [400,416) stays zero forever
__device__ __align__(16) __half g_hbt[(size_t)NB * TT * 416];
// w1 padded: [256 rows][KG]
__device__ __align__(16) __half g_w1p[(size_t)256 * KG];
// recurrence weights, interleaved rows (u*4+g), [layer][dir][800][KR]
__device__ __align__(16) __half g_wr[(size_t)2 * 2 * 800 * KR];

// ---------------- helpers ----------------
__device__ __forceinline__ float tanhapx(float x) {
    float y;
    asm("tanh.approx.f32 %0, %1;" : "=f"(y) : "f"(x));
    return y;
}
__device__ __forceinline__ __half2 tanh2(__half2 x) {
    __half2 y;
    asm("tanh.approx.f16x2 %0, %1;" : "=r"(*(uint32_t*)&y) : "r"(*(uint32_t*)&x));
    return y;
}
__device__ __forceinline__ __half2 sig2(__half2 x) {
    const __half2 h = __float2half2_rn(0.5f);
    return __hfma2(h, tanh2(__hmul2(x, h)), h);
}
__device__ __forceinline__ uint32_t smem_u32(const void* p) {
    uint32_t a;
    asm("{ .reg .u64 t; cvta.to.shared.u64 t, %1; cvt.u32.u64 %0, t; }" : "=r"(a) : "l"(p));
    return a;
}
__device__ __forceinline__ void ldsm_x4(uint32_t addr, uint32_t r[4]) {
    asm volatile("ldmatrix.sync.aligned.m8n8.x4.shared.b16 {%0,%1,%2,%3}, [%4];"
        : "=r"(r[0]), "=r"(r[1]), "=r"(r[2]), "=r"(r[3]) : "r"(addr));
}
__device__ __forceinline__ void mma16816h(float d[4], const uint32_t a[4],
                                          uint32_t b0, uint32_t b1) {
    asm volatile(
        "mma.sync.aligned.m16n8k16.row.col.f32.f16.f16.f32 "
        "{%0,%1,%2,%3}, {%4,%5,%6,%7}, {%8,%9}, {%0,%1,%2,%3};"
        : "+f"(d[0]), "+f"(d[1]), "+f"(d[2]), "+f"(d[3])
        : "r"(a[0]), "r"(a[1]), "r"(a[2]), "r"(a[3]), "r"(b0), "r"(b1));
}
__device__ __forceinline__ void cpasync16(uint32_t dst, const void* src) {
    asm volatile("cp.async.cg.shared.global [%0], [%1], 16;" :: "r"(dst), "l"(src));
}

// ---------------- embedding -> fp16, (t, b, k) padded to KP0 ----------------
__global__ __launch_bounds__(256) void k_embsplit(const int* __restrict__ tokens,
                                                  const float* __restrict__ emb) {
    int t = blockIdx.x;
    __shared__ int stok[NB];
    if (threadIdx.x < NB) stok[threadIdx.x] = tokens[t * NB + threadIdx.x];
    __syncthreads();
    size_t base = (size_t)t * NB * KP0;
    for (int idx = threadIdx.x; idx < NB * KP0; idx += 256) {
        int b = idx / KP0, k = idx - b * KP0;
        float v = (k < 200) ? __ldg(&emb[(size_t)stok[b] * 200 + k]) : 0.f;
        g_x[base + idx] = __float2half_rn(v);
    }
}

// ---------------- ALL weight prep (fp16 single) ----------------
__global__ __launch_bounds__(256) void k_prepw(
    const float* __restrict__ w0f, const float* __restrict__ w0b,
    const float* __restrict__ w1f, const float* __restrict__ w1b,
    const float* __restrict__ r0f, const float* __restrict__ r0b,
    const float* __restrict__ r1f, const float* __restrict__ r1b,
    const float* __restrict__ w1)
{
    int sel = blockIdx.y;
    int idx = blockIdx.x * 256 + threadIdx.x;
    if (sel < 4) {
        int layer = sel >> 1, dirv = sel & 1;
        const float* w = (sel == 0) ? w0f : (sel == 1) ? w0b : (sel == 2) ? w1f : w1b;
        int K = layer ? 400 : 200;
        int KPv = layer ? KP1 : KP0;
        if (idx >= 896 * KPv) return;
        __half* d = (layer ? g_w1 : g_w0) + (size_t)dirv * 896 * KPv;
        int m = idx / KPv, k = idx - m * KPv;
        float v = (m < 800 && k < K) ? __ldg(&w[(size_t)m * K + k]) : 0.f;
        d[idx] = __float2half_rn(v);
    } else if (sel < 8) {
        int layer = (sel - 4) >> 1, dirv = (sel - 4) & 1;
        const float* w = (sel == 4) ? r0f : (sel == 5) ? r0b : (sel == 6) ? r1f : r1b;
        if (idx >= 800 * KR) return;
        int r = idx / KR, k = idx - r * KR;
        int u = r >> 2, g = r & 3;
        float v = (k < 200) ? __ldg(&w[(size_t)(g * 200 + u) * 200 + k]) : 0.f;
        g_wr[((size_t)(layer * 2 + dirv) * 800 + r) * KR + k] = __float2half_rn(v);
    } else {
        if (idx >= 256 * KG) return;
        int n = idx / KG, kk = idx - n * KG;
        float v = 0.f;
        if (n < 200) {
            if (kk < 400) v = __ldg(&w1[(size_t)n * 800 + kk]);
            else if (kk >= 416 && kk < 816) v = __ldg(&w1[(size_t)n * 800 + kk - 16]);
        }
        g_w1p[idx] = __float2half_rn(v);
    }
}

// ---------------- tensor-core pre-GEMM (fp16 single) ----------------
__global__ __launch_bounds__(256) void k_gemm_mma(
    int layer,
    const float* __restrict__ bih_f, const float* __restrict__ bhh_f,
    const float* __restrict__ bih_b, const float* __restrict__ bhh_b)
{
    __shared__ __align__(16) __half sA[128 * AP];
    __shared__ __align__(16) __half sB[128 * AP];

    const int tid = threadIdx.x;
    const int warp = tid >> 5, lane = tid & 31;
    const int m0 = blockIdx.x * 128;
    const int t = blockIdx.y;
    const int dir = blockIdx.z;
    const int KPv = layer ? KP1 : KP0;
    const int nchunk = KPv >> 5;
    const __half* A = (layer ? g_w1 : g_w0) + (size_t)dir * 896 * KPv + (size_t)m0 * KPv;
    const __half* B = (layer ? g_h0 : g_x) + (size_t)t * NB * KPv;

    const int wm = (warp & 3) * 32;
    const int wn = (warp >> 2) * 64;
    const int lrow = lane & 15;
    const int lcol = (lane >> 4) * 8;

    const uint32_t aA = smem_u32(sA), aB = smem_u32(sB);

    float acc[2][8][4];
#pragma unroll
    for (int i = 0; i < 2; i++)
#pragma unroll
        for (int n = 0; n < 8; n++)
#pragma unroll
            for (int q = 0; q < 4; q++) acc[i][n][q] = 0.f;

    const int srow = tid >> 2;
    const int skv = (tid & 3) * 8;

    for (int c = 0; c < nchunk; c++) {
        const int kb0 = c * 32;
#pragma unroll
        for (int jv = 0; jv < 2; jv++) {
            int row = srow + jv * 64;
            size_t go = (size_t)row * KPv + kb0 + skv;
            int so = row * AP + skv;
            *(uint4*)&sA[so] = *(const uint4*)(A + go);
            *(uint4*)&sB[so] = *(const uint4*)(B + go);
        }
        __syncthreads();
#pragma unroll
        for (int ks = 0; ks < 2; ks++) {
            const int kb = ks * 16;
            uint32_t ah[2][4];
#pragma unroll
            for (int i = 0; i < 2; i++) {
                uint32_t off = (uint32_t)(((wm + i * 16 + lrow) * AP + kb + lcol) * 2);
                ldsm_x4(aA + off, ah[i]);
            }
#pragma unroll
            for (int p = 0; p < 4; p++) {
                uint32_t off = (uint32_t)(((wn + p * 16 + lrow) * AP + kb + lcol) * 2);
                uint32_t bh[4];
                ldsm_x4(aB + off, bh);
#pragma unroll
                for (int i = 0; i < 2; i++) {
                    mma16816h(acc[i][2 * p],     ah[i], bh[0], bh[2]);
                    mma16816h(acc[i][2 * p + 1], ah[i], bh[1], bh[3]);
                }
            }
        }
        __syncthreads();
    }

    const float* b1 = dir ? bih_b : bih_f;
    const float* b2 = dir ? bhh_b : bhh_f;
    float* outp = (dir ? g_pre_b : g_pre_f) + ((size_t)t * 800 + m0) * NB;
#pragma unroll
    for (int i = 0; i < 2; i++) {
#pragma unroll
        for (int half = 0; half < 2; half++) {
            int ml = wm + i * 16 + half * 8 + (lane >> 2);
            if (m0 + ml < 800) {
                float bs = __ldg(&b1[m0 + ml]) + __ldg(&b2[m0 + ml]);
                float* op = outp + (size_t)ml * NB + wn + (lane & 3) * 2;
#pragma unroll
                for (int n = 0; n < 8; n++) {
                    float2 v = make_float2(acc[i][n][half * 2] + bs,
                                           acc[i][n][half * 2 + 1] + bs);
                    *(float2*)(op + n * 8) = v;
                }
            }
        }
    }
}

// ---------------- cluster recurrence: 32 CTAs x 512 thr = 8 clusters of 4 -------
// Cluster = (dir, bslice of 32 batch cols); ranks = 4 ugroups of 50 units.
// W resident in smem; h exchanged via DSMEM push + cluster barrier.
// Gates: half2 unit-pairs via tanh.approx.f16x2 (5 MUFU per 2 items).
// smem: W [208][216] f16 @0 (89856) | hbuf 2x[32][216] f16 @89856 (27648) |
//       D [208][33] f32 @117504 (27456) | hsm [32][52] f16 @144960 (3328) = 148288
#define RS_H 89856
#define RS_D 117504
#define RS_HS 144960
#define RSMEM3 148288
__global__ __launch_bounds__(512) __cluster_dims__(4, 1, 1)
void k_recur_mma(int layer)
{
    extern __shared__ __align__(16) char dsm[];
    const uint32_t sb = smem_u32(dsm);
    const uint32_t sW = sb;
    const uint32_t sH = sb + RS_H;
    float* Dsm = (float*)(dsm + RS_D);
    __half* hsm = (__half*)(dsm + RS_HS);

    const int tid = threadIdx.x;
    const int warp = tid >> 5, lane = tid & 31;
    const int grp = blockIdx.x >> 2;       // 0..7
    const int ug = blockIdx.x & 3;         // cluster rank
    const int dir = grp >> 2;
    const int bs = grp & 3;
    const int b0 = bs * 32;
    const int lrow = lane & 15, lcol = (lane >> 4) * 8;

    const __half* wr = g_wr + ((size_t)(layer * 2 + dir) * 800 + (size_t)ug * 200) * KR;
    const float* pre = dir ? g_pre_b : g_pre_f;

    // stage resident W (200 rows x 208), zero pad rows 200..207, zero both h bufs
    for (int i = tid; i < 5200; i += 512) {
        int r = i / 26, seg = i - r * 26;
        cpasync16(sW + (uint32_t)((r * 216 + seg * 8) * 2), wr + (size_t)r * KR + seg * 8);
    }
    asm volatile("cp.async.commit_group;" ::: "memory");
    for (int i = tid; i < 864; i += 512)
        ((uint32_t*)(dsm + 200 * 216 * 2))[i] = 0u;
    for (int i = tid; i < 6912; i += 512)
        ((uint32_t*)(dsm + RS_H))[i] = 0u;
    asm volatile("cp.async.wait_group 0;" ::: "memory");
    __syncthreads();
    asm volatile("barrier.cluster.arrive.aligned;" ::: "memory");
    asm volatile("barrier.cluster.wait.aligned;" ::: "memory");

    __half2 cc2[2] = {__float2half2_rn(0.f), __float2half2_rn(0.f)};

    for (int s = 0; s < TT; s++) {
        const int t = dir ? (TT - 1 - s) : s;
        const uint32_t hcur = sH + (uint32_t)(s & 1) * 13824u;

        // pre-activations loaded directly as accumulator init (1 M-tile per warp)
        float acc[4][4];
        const float* pt = pre + (size_t)t * 800 * NB + b0;
        const bool va = (warp < 13);
#pragma unroll
        for (int p = 0; p < 4; p++) {
            int c = p * 8 + (lane & 3) * 2;
#pragma unroll
            for (int hh = 0; hh < 2; hh++) {
                int r = warp * 16 + (lane >> 2) + hh * 8;
                float2 v = make_float2(0.f, 0.f);
                if (va && r < 200) {
                    int prow = (r & 3) * 200 + ug * 50 + (r >> 2);
                    v = *(const float2*)&pt[(size_t)prow * NB + c];
                }
                acc[p][hh * 2] = v.x;
                acc[p][hh * 2 + 1] = v.y;
            }
        }

        // MMA: D[208x32] = W @ h ; one M-tile per warp (warps 0..12)
        if (va) {
#pragma unroll
            for (int ko = 0; ko < 13; ko++) {
                uint32_t bf0[4], bf1[4], a4[4];
                ldsm_x4(hcur + (uint32_t)((lrow * 216 + ko * 16 + lcol) * 2), bf0);
                ldsm_x4(hcur + (uint32_t)(((16 + lrow) * 216 + ko * 16 + lcol) * 2), bf1);
                ldsm_x4(sW + (uint32_t)(((warp * 16 + lrow) * 216 + ko * 16 + lcol) * 2), a4);
                mma16816h(acc[0], a4, bf0[0], bf0[2]);
                mma16816h(acc[1], a4, bf0[1], bf0[3]);
                mma16816h(acc[2], a4, bf1[0], bf1[2]);
                mma16816h(acc[3], a4, bf1[1], bf1[3]);
            }
            int r = warp * 16 + (lane >> 2);
#pragma unroll
            for (int p = 0; p < 4; p++) {
                int c = p * 8 + (lane & 3) * 2;
                Dsm[r * 33 + c] = acc[p][0];
                Dsm[r * 33 + c + 1] = acc[p][1];
                Dsm[(r + 8) * 33 + c] = acc[p][2];
                Dsm[(r + 8) * 33 + c + 1] = acc[p][3];
            }
        }
        __syncthreads();

        // gates: half2 item = units (2up, 2up+1) x one col; 800 pairs
#pragma unroll
        for (int k = 0; k < 2; k++) {
            int i = tid + k * 512;
            if (i < 800) {
                int up = i >> 5, col = i & 31;
                int rb = up * 8;
                __half2 gi = __floats2half2_rn(Dsm[(rb + 0) * 33 + col], Dsm[(rb + 4) * 33 + col]);
                __half2 gf = __floats2half2_rn(Dsm[(rb + 1) * 33 + col], Dsm[(rb + 5) * 33 + col]);
                __half2 gg = __floats2half2_rn(Dsm[(rb + 2) * 33 + col], Dsm[(rb + 6) * 33 + col]);
                __half2 go = __floats2half2_rn(Dsm[(rb + 3) * 33 + col], Dsm[(rb + 7) * 33 + col]);
                __half2 cv = __hfma2(sig2(gf), cc2[k], __hmul2(sig2(gi), tanh2(gg)));
                cc2[k] = cv;
                __half2 hv = __hmul2(sig2(go), tanh2(cv));
                *(uint32_t*)&hsm[col * 52 + up * 2] = *(uint32_t*)&hv;
            }
        }
        __syncthreads();

        // DSMEM push: my 50-unit slice -> all 4 cluster CTAs' next h buffer
        const uint32_t hnloc = sH + (uint32_t)((s + 1) & 1) * 13824u;
        for (int i = tid; i < 800; i += 512) {
            int col = i / 25, q = i - col * 25;
            uint32_t v = *(uint32_t*)&hsm[col * 52 + q * 2];
            uint32_t loc = hnloc + (uint32_t)((col * 216 + ug * 50 + q * 2) * 2);
#pragma unroll
            for (int rk = 0; rk < 4; rk++) {
                uint32_t pa;
                asm("mapa.shared::cluster.u32 %0, %1, %2;" : "=r"(pa) : "r"(loc), "r"(rk));
                asm volatile("st.shared::cluster.u32 [%0], %1;" :: "r"(pa), "r"(v) : "memory");
            }
        }
        asm volatile("barrier.cluster.arrive.aligned;" ::: "memory");

        // layer-output gmem stores overlap the barrier skew window
        for (int i = tid; i < 800; i += 512) {
            int col = i / 25, q = i - col * 25;
            uint32_t v = *(uint32_t*)&hsm[col * 52 + q * 2];
            if (layer == 0) {
                size_t o = ((size_t)t * NB + b0 + col) * KP1 + dir * 200 + ug * 50 + q * 2;
                *(uint32_t*)&g_h0[o] = v;
            } else {
                size_t o = ((size_t)(b0 + col) * TT + t) * 416 + dir * 200 + ug * 50 + q * 2;
                *(uint32_t*)&g_hbt[o] = v;
            }
        }
        asm volatile("barrier.cluster.wait.aligned;" ::: "memory");
    }
}

// ---------------- tensor-core path-gather + MLP1 (tanh), fp16 single ----------------
__global__ __launch_bounds__(256) void k_gather_mma(
    const int* __restrict__ paths, const float* __restrict__ b1)
{
    __shared__ __align__(16) __half sA[128 * AP];
    __shared__ __align__(16) __half sB[128 * AP];
    __shared__ long long abase[128][2];

    const int tid = threadIdx.x;
    const int warp = tid >> 5, lane = tid & 31;
    const int s0 = blockIdx.x * 128;
    const int n0 = blockIdx.y * 128;

    {
        int i = tid >> 1, j = tid & 1;
        int s = s0 + i;
        int tval = paths[(size_t)s * 2 + j];
        int b = s >> 8;
        abase[i][j] = (tval >= 0) ? ((long long)b * TT + tval) * 416LL : -1LL;
    }
    __syncthreads();

    const int wm = (warp & 3) * 32;
    const int wn = (warp >> 2) * 64;
    const int lrow = lane & 15;
    const int lcol = (lane >> 4) * 8;

    const uint32_t aA = smem_u32(sA), aB = smem_u32(sB);

    float acc[2][8][4];
#pragma unroll
    for (int i = 0; i < 2; i++)
#pragma unroll
        for (int n = 0; n < 8; n++)
#pragma unroll
            for (int q = 0; q < 4; q++) acc[i][n][q] = 0.f;

    const int srow = tid >> 2;
    const int skv = (tid & 3) * 8;

    for (int c = 0; c < 26; c++) {
        const int j = (c >= 13) ? 1 : 0;
        const int kloc = c * 32 - j * 416 + skv;
        const int kb0 = c * 32;
#pragma unroll
        for (int jv = 0; jv < 2; jv++) {
            int row = srow + jv * 64;
            int so = row * AP + skv;
            long long ab = abase[row][j];
            uint4 vh = make_uint4(0u, 0u, 0u, 0u);
            if (ab >= 0) vh = *(const uint4*)(g_hbt + ab + kloc);
            *(uint4*)&sA[so] = vh;
            *(uint4*)&sB[so] = *(const uint4*)(g_w1p + (size_t)(n0 + row) * KG + kb0 + skv);
        }
        __syncthreads();
#pragma unroll
        for (int ks = 0; ks < 2; ks++) {
            const int kb = ks * 16;
            uint32_t ah[2][4];
#pragma unroll
            for (int i = 0; i < 2; i++) {
                uint32_t off = (uint32_t)(((wm + i * 16 + lrow) * AP + kb + lcol) * 2);
                ldsm_x4(aA + off, ah[i]);
            }
#pragma unroll
            for (int p = 0; p < 4; p++) {
                uint32_t off = (uint32_t)(((wn + p * 16 + lrow) * AP + kb + lcol) * 2);
                uint32_t bh[4];
                ldsm_x4(aB + off, bh);
#pragma unroll
                for (int i = 0; i < 2; i++) {
                    mma16816h(acc[i][2 * p],     ah[i], bh[0], bh[2]);
                    mma16816h(acc[i][2 * p + 1], ah[i], bh[1], bh[3]);
                }
            }
        }
        __syncthreads();
    }

#pragma unroll
    for (int i = 0; i < 2; i++) {
#pragma unroll
        for (int half = 0; half < 2; half++) {
            int ml = wm + i * 16 + half * 8 + (lane >> 2);
            int s = s0 + ml;
#pragma unroll
            for (int n = 0; n < 8; n++) {
                int nn = n0 + wn + (lane & 3) * 2 + n * 8;
                if (nn < 200) {
                    float2 v = make_float2(
                        tanhapx(acc[i][n][half * 2] + __ldg(&b1[nn])),
                        tanhapx(acc[i][n][half * 2 + 1] + __ldg(&b1[nn + 1])));
                    *(float2*)&g_hid[(size_t)s * 200 + nn] = v;
                }
            }
        }
    }
}

// ---------------- MLP2 + softmax: one warp per sample ----------------
__global__ __launch_bounds__(128) void k_mlp2(
    const float* __restrict__ w2, const float* __restrict__ b2, float* __restrict__ out)
{
    __shared__ float w2s[800];
    __shared__ float b2s[4];
    const int tid = threadIdx.x;
    for (int i = tid; i < 800; i += 128) w2s[i] = w2[i];
    if (tid < 4) b2s[tid] = b2[tid];
    __syncthreads();
    const int warp = tid >> 5, lane = tid & 31;
    const int s = blockIdx.x * 4 + warp;
    const float* hr = g_hid + (size_t)s * 200;
    float a0 = 0.f, a1 = 0.f, a2 = 0.f, a3 = 0.f;
    for (int k = lane; k < 200; k += 32) {
        float h = hr[k];
        a0 += h * w2s[k];
        a1 += h * w2s[200 + k];
        a2 += h * w2s[400 + k];
        a3 += h * w2s[600 + k];
    }
#pragma unroll
    for (int o = 16; o > 0; o >>= 1) {
        a0 += __shfl_down_sync(0xffffffffu, a0, o);
        a1 += __shfl_down_sync(0xffffffffu, a1, o);
        a2 += __shfl_down_sync(0xffffffffu, a2, o);
        a3 += __shfl_down_sync(0xffffffffu, a3, o);
    }
    if (lane == 0) {
        float l0 = a0 + b2s[0], l1 = a1 + b2s[1], l2 = a2 + b2s[2], l3 = a3 + b2s[3];
        float m = fmaxf(fmaxf(l0, l1), fmaxf(l2, l3));
        float e0 = expf(l0 - m), e1 = expf(l1 - m), e2 = expf(l2 - m), e3 = expf(l3 - m);
        float inv = 1.f / (e0 + e1 + e2 + e3);
        float4 r = make_float4(e0 * inv, e1 * inv, e2 * inv, e3 * inv);
        *(float4*)&out[(size_t)s * 4] = r;
    }
}

extern "C" void kernel_launch(void* const* d_in, const int* in_sizes, int n_in,
                              void* d_out, int out_size)
{
    const int* tokens = (const int*)d_in[0];
    const int* paths = (const int*)d_in[1];
    const float* emb = (const float*)d_in[2];
    const float* wih0f = (const float*)d_in[3];
    const float* whh0f = (const float*)d_in[4];
    const float* bih0f = (const float*)d_in[5];
    const float* bhh0f = (const float*)d_in[6];
    const float* wih0b = (const float*)d_in[7];
    const float* whh0b = (const float*)d_in[8];
    const float* bih0b = (const float*)d_in[9];
    const float* bhh0b = (const float*)d_in[10];
    const float* wih1f = (const float*)d_in[11];
    const float* whh1f = (const float*)d_in[12];
    const float* bih1f = (const float*)d_in[13];
    const float* bhh1f = (const float*)d_in[14];
    const float* wih1b = (const float*)d_in[15];
    const float* whh1b = (const float*)d_in[16];
    const float* bih1b = (const float*)d_in[17];
    const float* bhh1b = (const float*)d_in[18];
    const float* w1 = (const float*)d_in[19];
    const float* b1 = (const float*)d_in[20];
    const float* w2 = (const float*)d_in[21];
    const float* b2 = (const float*)d_in[22];
    float* out = (float*)d_out;

    cudaFuncSetAttribute(k_recur_mma, cudaFuncAttributeMaxDynamicSharedMemorySize, RSMEM3);

    k_embsplit<<<TT, 256>>>(tokens, emb);                               // launch 1
    dim3 gw((896 * KP1 + 255) / 256, 9);
    k_prepw<<<gw, 256>>>(wih0f, wih0b, wih1f, wih1b,
                         whh0f, whh0b, whh1f, whh1b, w1);               // launch 2

    dim3 gg(7, TT, 2);
    k_gemm_mma<<<gg, 256>>>(0, bih0f, bhh0f, bih0b, bhh0b);             // launch 3
    k_recur_mma<<<32, 512, RSMEM3>>>(0);                                // launch 4 (profiled)
    k_gemm_mma<<<gg, 256>>>(1, bih1f, bhh1f, bih1b, bhh1b);             // launch 5
    k_recur_mma<<<32, 512, RSMEM3>>>(1);                                // launch 6

    dim3 g4(NSAMP / 128, 2);
    k_gather_mma<<<g4, 256>>>(paths, b1);                               // launch 7
    k_mlp2<<<NSAMP / 4, 128>>>(w2, b2, out);                            // launch 8
}

// round 17
// speedup vs baseline: 2.5567x; 1.0532x over previous
#include <cuda_runtime.h>
#include <cuda_fp16.h>
#include <cstdint>

#define TT 512
#define NB 128
#define NSAMP 32768
#define KP0 224
#define KP1 416
#define AP 40    // GEMM smem stride (elems) for 32-wide k chunks
#define KR 208   // recurrence padded K (13 x k16)
#define KG 832   // gather-MLP padded K (2 x 416)

// ---------------- static scratch (no allocation; zero-initialized at load) -------
__device__ float g_pre_f[(size_t)TT * 800 * NB];   // (t, gate, b)
__device__ float g_pre_b[(size_t)TT * 800 * NB];
__device__ float g_hid[(size_t)NSAMP * 200];       // MLP hidden (s, n)

// fp16 single-precision operand buffers (error model calibrated round 10)
__device__ __align__(16) __half g_w0[(size_t)2 * 896 * KP0];  // [dir][m][k]
__device__ __align__(16) __half g_w1[(size_t)2 * 896 * KP1];
__device__ __align__(16) __half g_x[(size_t)TT * NB * KP0];   // (t, b, k)
__device__ __align__(16) __half g_h0[(size_t)TT * NB * KP1];  // layer0 out (t,b,k)
// layer1 out, (b, t, u) padded to 416; pad region [400,416) stays zero forever
__device__ __align__(16) __half g_hbt[(size_t)NB * TT * 416];
// w1 padded: [256 rows][KG]
__device__ __align__(16) __half g_w1p[(size_t)256 * KG];
// recurrence weights, interleaved rows (u*4+g), [layer][dir][800][KR]
__device__ __align__(16) __half g_wr[(size_t)2 * 2 * 800 * KR];

// ---------------- helpers ----------------
__device__ __forceinline__ float tanhapx(float x) {
    float y;
    asm("tanh.approx.f32 %0, %1;" : "=f"(y) : "f"(x));
    return y;
}
__device__ __forceinline__ __half2 tanh2(__half2 x) {
    __half2 y;
    asm("tanh.approx.f16x2 %0, %1;" : "=r"(*(uint32_t*)&y) : "r"(*(uint32_t*)&x));
    return y;
}
__device__ __forceinline__ __half2 sig2(__half2 x) {
    const __half2 h = __float2half2_rn(0.5f);
    return __hfma2(h, tanh2(__hmul2(x, h)), h);
}
__device__ __forceinline__ uint32_t smem_u32(const void* p) {
    uint32_t a;
    asm("{ .reg .u64 t; cvta.to.shared.u64 t, %1; cvt.u32.u64 %0, t; }" : "=r"(a) : "l"(p));
    return a;
}
__device__ __forceinline__ void ldsm_x4(uint32_t addr, uint32_t r[4]) {
    asm volatile("ldmatrix.sync.aligned.m8n8.x4.shared.b16 {%0,%1,%2,%3}, [%4];"
        : "=r"(r[0]), "=r"(r[1]), "=r"(r[2]), "=r"(r[3]) : "r"(addr));
}
__device__ __forceinline__ void mma16816h(float d[4], const uint32_t a[4],
                                          uint32_t b0, uint32_t b1) {
    asm volatile(
        "mma.sync.aligned.m16n8k16.row.col.f32.f16.f16.f32 "
        "{%0,%1,%2,%3}, {%4,%5,%6,%7}, {%8,%9}, {%0,%1,%2,%3};"
        : "+f"(d[0]), "+f"(d[1]), "+f"(d[2]), "+f"(d[3])
        : "r"(a[0]), "r"(a[1]), "r"(a[2]), "r"(a[3]), "r"(b0), "r"(b1));
}
__device__ __forceinline__ void cpasync16(uint32_t dst, const void* src) {
    asm volatile("cp.async.cg.shared.global [%0], [%1], 16;" :: "r"(dst), "l"(src));
}

// ---------------- embedding -> fp16, (t, b, k) padded to KP0 ----------------
__global__ __launch_bounds__(256) void k_embsplit(const int* __restrict__ tokens,
                                                  const float* __restrict__ emb) {
    int t = blockIdx.x;
    __shared__ int stok[NB];
    if (threadIdx.x < NB) stok[threadIdx.x] = tokens[t * NB + threadIdx.x];
    __syncthreads();
    size_t base = (size_t)t * NB * KP0;
    for (int idx = threadIdx.x; idx < NB * KP0; idx += 256) {
        int b = idx / KP0, k = idx - b * KP0;
        float v = (k < 200) ? __ldg(&emb[(size_t)stok[b] * 200 + k]) : 0.f;
        g_x[base + idx] = __float2half_rn(v);
    }
}

// ---------------- ALL weight prep (fp16 single) ----------------
__global__ __launch_bounds__(256) void k_prepw(
    const float* __restrict__ w0f, const float* __restrict__ w0b,
    const float* __restrict__ w1f, const float* __restrict__ w1b,
    const float* __restrict__ r0f, const float* __restrict__ r0b,
    const float* __restrict__ r1f, const float* __restrict__ r1b,
    const float* __restrict__ w1)
{
    int sel = blockIdx.y;
    int idx = blockIdx.x * 256 + threadIdx.x;
    if (sel < 4) {
        int layer = sel >> 1, dirv = sel & 1;
        const float* w = (sel == 0) ? w0f : (sel == 1) ? w0b : (sel == 2) ? w1f : w1b;
        int K = layer ? 400 : 200;
        int KPv = layer ? KP1 : KP0;
        if (idx >= 896 * KPv) return;
        __half* d = (layer ? g_w1 : g_w0) + (size_t)dirv * 896 * KPv;
        int m = idx / KPv, k = idx - m * KPv;
        float v = (m < 800 && k < K) ? __ldg(&w[(size_t)m * K + k]) : 0.f;
        d[idx] = __float2half_rn(v);
    } else if (sel < 8) {
        int layer = (sel - 4) >> 1, dirv = (sel - 4) & 1;
        const float* w = (sel == 4) ? r0f : (sel == 5) ? r0b : (sel == 6) ? r1f : r1b;
        if (idx >= 800 * KR) return;
        int r = idx / KR, k = idx - r * KR;
        int u = r >> 2, g = r & 3;
        float v = (k < 200) ? __ldg(&w[(size_t)(g * 200 + u) * 200 + k]) : 0.f;
        g_wr[((size_t)(layer * 2 + dirv) * 800 + r) * KR + k] = __float2half_rn(v);
    } else {
        if (idx >= 256 * KG) return;
        int n = idx / KG, kk = idx - n * KG;
        float v = 0.f;
        if (n < 200) {
            if (kk < 400) v = __ldg(&w1[(size_t)n * 800 + kk]);
            else if (kk >= 416 && kk < 816) v = __ldg(&w1[(size_t)n * 800 + kk - 16]);
        }
        g_w1p[idx] = __float2half_rn(v);
    }
}

// ---------------- tensor-core pre-GEMM (fp16 single) ----------------
__global__ __launch_bounds__(256) void k_gemm_mma(
    int layer,
    const float* __restrict__ bih_f, const float* __restrict__ bhh_f,
    const float* __restrict__ bih_b, const float* __restrict__ bhh_b)
{
    __shared__ __align__(16) __half sA[128 * AP];
    __shared__ __align__(16) __half sB[128 * AP];

    const int tid = threadIdx.x;
    const int warp = tid >> 5, lane = tid & 31;
    const int m0 = blockIdx.x * 128;
    const int t = blockIdx.y;
    const int dir = blockIdx.z;
    const int KPv = layer ? KP1 : KP0;
    const int nchunk = KPv >> 5;
    const __half* A = (layer ? g_w1 : g_w0) + (size_t)dir * 896 * KPv + (size_t)m0 * KPv;
    const __half* B = (layer ? g_h0 : g_x) + (size_t)t * NB * KPv;

    const int wm = (warp & 3) * 32;
    const int wn = (warp >> 2) * 64;
    const int lrow = lane & 15;
    const int lcol = (lane >> 4) * 8;

    const uint32_t aA = smem_u32(sA), aB = smem_u32(sB);

    float acc[2][8][4];
#pragma unroll
    for (int i = 0; i < 2; i++)
#pragma unroll
        for (int n = 0; n < 8; n++)
#pragma unroll
            for (int q = 0; q < 4; q++) acc[i][n][q] = 0.f;

    const int srow = tid >> 2;
    const int skv = (tid & 3) * 8;

    for (int c = 0; c < nchunk; c++) {
        const int kb0 = c * 32;
#pragma unroll
        for (int jv = 0; jv < 2; jv++) {
            int row = srow + jv * 64;
            size_t go = (size_t)row * KPv + kb0 + skv;
            int so = row * AP + skv;
            *(uint4*)&sA[so] = *(const uint4*)(A + go);
            *(uint4*)&sB[so] = *(const uint4*)(B + go);
        }
        __syncthreads();
#pragma unroll
        for (int ks = 0; ks < 2; ks++) {
            const int kb = ks * 16;
            uint32_t ah[2][4];
#pragma unroll
            for (int i = 0; i < 2; i++) {
                uint32_t off = (uint32_t)(((wm + i * 16 + lrow) * AP + kb + lcol) * 2);
                ldsm_x4(aA + off, ah[i]);
            }
#pragma unroll
            for (int p = 0; p < 4; p++) {
                uint32_t off = (uint32_t)(((wn + p * 16 + lrow) * AP + kb + lcol) * 2);
                uint32_t bh[4];
                ldsm_x4(aB + off, bh);
#pragma unroll
                for (int i = 0; i < 2; i++) {
                    mma16816h(acc[i][2 * p],     ah[i], bh[0], bh[2]);
                    mma16816h(acc[i][2 * p + 1], ah[i], bh[1], bh[3]);
                }
            }
        }
        __syncthreads();
    }

    const float* b1 = dir ? bih_b : bih_f;
    const float* b2 = dir ? bhh_b : bhh_f;
    float* outp = (dir ? g_pre_b : g_pre_f) + ((size_t)t * 800 + m0) * NB;
#pragma unroll
    for (int i = 0; i < 2; i++) {
#pragma unroll
        for (int half = 0; half < 2; half++) {
            int ml = wm + i * 16 + half * 8 + (lane >> 2);
            if (m0 + ml < 800) {
                float bs = __ldg(&b1[m0 + ml]) + __ldg(&b2[m0 + ml]);
                float* op = outp + (size_t)ml * NB + wn + (lane & 3) * 2;
#pragma unroll
                for (int n = 0; n < 8; n++) {
                    float2 v = make_float2(acc[i][n][half * 2] + bs,
                                           acc[i][n][half * 2 + 1] + bs);
                    *(float2*)(op + n * 8) = v;
                }
            }
        }
    }
}

// ---------------- cluster recurrence: 32 CTAs x 512 thr = 8 clusters of 4 -------
// Cluster = (dir, bslice of 32 batch cols); ranks = 4 ugroups of 50 units.
// W resident in REGISTERS (13 ldsm fragments loaded once); pre-activations
// software-pipelined (prefetched into registers during the barrier window).
// h exchanged via DSMEM push + cluster barrier. Gates: tanh.approx.f16x2.
// smem: W [208][216] f16 @0 (89856) | hbuf 2x[32][216] f16 @89856 (27648) |
//       D [208][33] f32 @117504 (27456) | hsm [32][52] f16 @144960 (3328) = 148288
#define RS_H 89856
#define RS_D 117504
#define RS_HS 144960
#define RSMEM3 148288
__global__ __launch_bounds__(512) __cluster_dims__(4, 1, 1)
void k_recur_mma(int layer)
{
    extern __shared__ __align__(16) char dsm[];
    const uint32_t sb = smem_u32(dsm);
    const uint32_t sW = sb;
    const uint32_t sH = sb + RS_H;
    float* Dsm = (float*)(dsm + RS_D);
    __half* hsm = (__half*)(dsm + RS_HS);

    const int tid = threadIdx.x;
    const int warp = tid >> 5, lane = tid & 31;
    const int grp = blockIdx.x >> 2;       // 0..7
    const int ug = blockIdx.x & 3;         // cluster rank
    const int dir = grp >> 2;
    const int bs = grp & 3;
    const int b0 = bs * 32;
    const int lrow = lane & 15, lcol = (lane >> 4) * 8;
    const bool va = (warp < 13);

    const __half* wr = g_wr + ((size_t)(layer * 2 + dir) * 800 + (size_t)ug * 200) * KR;
    const float* pre = dir ? g_pre_b : g_pre_f;

    // stage resident W (200 rows x 208), zero pad rows 200..207, zero both h bufs
    for (int i = tid; i < 5200; i += 512) {
        int r = i / 26, seg = i - r * 26;
        cpasync16(sW + (uint32_t)((r * 216 + seg * 8) * 2), wr + (size_t)r * KR + seg * 8);
    }
    asm volatile("cp.async.commit_group;" ::: "memory");
    for (int i = tid; i < 864; i += 512)
        ((uint32_t*)(dsm + 200 * 216 * 2))[i] = 0u;
    for (int i = tid; i < 6912; i += 512)
        ((uint32_t*)(dsm + RS_H))[i] = 0u;
    asm volatile("cp.async.wait_group 0;" ::: "memory");
    __syncthreads();
    asm volatile("barrier.cluster.arrive.aligned;" ::: "memory");
    asm volatile("barrier.cluster.wait.aligned;" ::: "memory");

    // W fragments -> registers, once (step-invariant)
    uint32_t wreg[13][4];
    if (va) {
#pragma unroll
        for (int ko = 0; ko < 13; ko++)
            ldsm_x4(sW + (uint32_t)(((warp * 16 + lrow) * 216 + ko * 16 + lcol) * 2), wreg[ko]);
    }

    __half2 cc2[2] = {__float2half2_rn(0.f), __float2half2_rn(0.f)};

    // pre-activation fragment prefetch for step 0
    const int pc = (lane & 3) * 2;
    const int pr0 = (lane >> 2);
    float2 pv[4][2];
    {
        const float* pt = pre + (size_t)(dir ? (TT - 1) : 0) * 800 * NB + b0;
#pragma unroll
        for (int p = 0; p < 4; p++)
#pragma unroll
            for (int hh = 0; hh < 2; hh++) {
                int r = warp * 16 + pr0 + hh * 8;
                float2 v = make_float2(0.f, 0.f);
                if (va && r < 200) {
                    int prow = (r & 3) * 200 + ug * 50 + (r >> 2);
                    v = *(const float2*)&pt[(size_t)prow * NB + p * 8 + pc];
                }
                pv[p][hh] = v;
            }
    }

    for (int s = 0; s < TT; s++) {
        const int t = dir ? (TT - 1 - s) : s;
        const uint32_t hcur = sH + (uint32_t)(s & 1) * 13824u;

        // accumulators init from prefetched pre fragments
        float acc[4][4];
#pragma unroll
        for (int p = 0; p < 4; p++) {
            acc[p][0] = pv[p][0].x;
            acc[p][1] = pv[p][0].y;
            acc[p][2] = pv[p][1].x;
            acc[p][3] = pv[p][1].y;
        }

        // MMA: D[208x32] = W @ h ; one M-tile per warp (warps 0..12)
        if (va) {
#pragma unroll
            for (int ko = 0; ko < 13; ko++) {
                uint32_t bf0[4], bf1[4];
                ldsm_x4(hcur + (uint32_t)((lrow * 216 + ko * 16 + lcol) * 2), bf0);
                ldsm_x4(hcur + (uint32_t)(((16 + lrow) * 216 + ko * 16 + lcol) * 2), bf1);
                mma16816h(acc[0], wreg[ko], bf0[0], bf0[2]);
                mma16816h(acc[1], wreg[ko], bf0[1], bf0[3]);
                mma16816h(acc[2], wreg[ko], bf1[0], bf1[2]);
                mma16816h(acc[3], wreg[ko], bf1[1], bf1[3]);
            }
            int r = warp * 16 + pr0;
#pragma unroll
            for (int p = 0; p < 4; p++) {
                int c = p * 8 + pc;
                Dsm[r * 33 + c] = acc[p][0];
                Dsm[r * 33 + c + 1] = acc[p][1];
                Dsm[(r + 8) * 33 + c] = acc[p][2];
                Dsm[(r + 8) * 33 + c + 1] = acc[p][3];
            }
        }
        __syncthreads();

        // gates: half2 item = units (2up, 2up+1) x one col; 800 pairs
#pragma unroll
        for (int k = 0; k < 2; k++) {
            int i = tid + k * 512;
            if (i < 800) {
                int up = i >> 5, col = i & 31;
                int rb = up * 8;
                __half2 gi = __floats2half2_rn(Dsm[(rb + 0) * 33 + col], Dsm[(rb + 4) * 33 + col]);
                __half2 gf = __floats2half2_rn(Dsm[(rb + 1) * 33 + col], Dsm[(rb + 5) * 33 + col]);
                __half2 gg = __floats2half2_rn(Dsm[(rb + 2) * 33 + col], Dsm[(rb + 6) * 33 + col]);
                __half2 go = __floats2half2_rn(Dsm[(rb + 3) * 33 + col], Dsm[(rb + 7) * 33 + col]);
                __half2 cv = __hfma2(sig2(gf), cc2[k], __hmul2(sig2(gi), tanh2(gg)));
                cc2[k] = cv;
                __half2 hv = __hmul2(sig2(go), tanh2(cv));
                *(uint32_t*)&hsm[col * 52 + up * 2] = *(uint32_t*)&hv;
            }
        }
        __syncthreads();

        // DSMEM push: my 50-unit slice -> all 4 cluster CTAs' next h buffer
        const uint32_t hnloc = sH + (uint32_t)((s + 1) & 1) * 13824u;
        for (int i = tid; i < 800; i += 512) {
            int col = i / 25, q = i - col * 25;
            uint32_t v = *(uint32_t*)&hsm[col * 52 + q * 2];
            uint32_t loc = hnloc + (uint32_t)((col * 216 + ug * 50 + q * 2) * 2);
#pragma unroll
            for (int rk = 0; rk < 4; rk++) {
                uint32_t pa;
                asm("mapa.shared::cluster.u32 %0, %1, %2;" : "=r"(pa) : "r"(loc), "r"(rk));
                asm volatile("st.shared::cluster.u32 [%0], %1;" :: "r"(pa), "r"(v) : "memory");
            }
        }
        asm volatile("barrier.cluster.arrive.aligned;" ::: "memory");

        // overlap the barrier skew window: prefetch next step's pre fragments
        if (s + 1 < TT) {
            const int tn = dir ? (TT - 2 - s) : (s + 1);
            const float* pt = pre + (size_t)tn * 800 * NB + b0;
#pragma unroll
            for (int p = 0; p < 4; p++)
#pragma unroll
                for (int hh = 0; hh < 2; hh++) {
                    int r = warp * 16 + pr0 + hh * 8;
                    float2 v = make_float2(0.f, 0.f);
                    if (va && r < 200) {
                        int prow = (r & 3) * 200 + ug * 50 + (r >> 2);
                        v = *(const float2*)&pt[(size_t)prow * NB + p * 8 + pc];
                    }
                    pv[p][hh] = v;
                }
        }
        // ... and the layer-output gmem stores
        for (int i = tid; i < 800; i += 512) {
            int col = i / 25, q = i - col * 25;
            uint32_t v = *(uint32_t*)&hsm[col * 52 + q * 2];
            if (layer == 0) {
                size_t o = ((size_t)t * NB + b0 + col) * KP1 + dir * 200 + ug * 50 + q * 2;
                *(uint32_t*)&g_h0[o] = v;
            } else {
                size_t o = ((size_t)(b0 + col) * TT + t) * 416 + dir * 200 + ug * 50 + q * 2;
                *(uint32_t*)&g_hbt[o] = v;
            }
        }
        asm volatile("barrier.cluster.wait.aligned;" ::: "memory");
    }
}

// ---------------- tensor-core path-gather + MLP1 (tanh), fp16 single ----------------
__global__ __launch_bounds__(256) void k_gather_mma(
    const int* __restrict__ paths, const float* __restrict__ b1)
{
    __shared__ __align__(16) __half sA[128 * AP];
    __shared__ __align__(16) __half sB[128 * AP];
    __shared__ long long abase[128][2];

    const int tid = threadIdx.x;
    const int warp = tid >> 5, lane = tid & 31;
    const int s0 = blockIdx.x * 128;
    const int n0 = blockIdx.y * 128;

    {
        int i = tid >> 1, j = tid & 1;
        int s = s0 + i;
        int tval = paths[(size_t)s * 2 + j];
        int b = s >> 8;
        abase[i][j] = (tval >= 0) ? ((long long)b * TT + tval) * 416LL : -1LL;
    }
    __syncthreads();

    const int wm = (warp & 3) * 32;
    const int wn = (warp >> 2) * 64;
    const int lrow = lane & 15;
    const int lcol = (lane >> 4) * 8;

    const uint32_t aA = smem_u32(sA), aB = smem_u32(sB);

    float acc[2][8][4];
#pragma unroll
    for (int i = 0; i < 2; i++)
#pragma unroll
        for (int n = 0; n < 8; n++)
#pragma unroll
            for (int q = 0; q < 4; q++) acc[i][n][q] = 0.f;

    const int srow = tid >> 2;
    const int skv = (tid & 3) * 8;

    for (int c = 0; c < 26; c++) {
        const int j = (c >= 13) ? 1 : 0;
        const int kloc = c * 32 - j * 416 + skv;
        const int kb0 = c * 32;
#pragma unroll
        for (int jv = 0; jv < 2; jv++) {
            int row = srow + jv * 64;
            int so = row * AP + skv;
            long long ab = abase[row][j];
            uint4 vh = make_uint4(0u, 0u, 0u, 0u);
            if (ab >= 0) vh = *(const uint4*)(g_hbt + ab + kloc);
            *(uint4*)&sA[so] = vh;
            *(uint4*)&sB[so] = *(const uint4*)(g_w1p + (size_t)(n0 + row) * KG + kb0 + skv);
        }
        __syncthreads();
#pragma unroll
        for (int ks = 0; ks < 2; ks++) {
            const int kb = ks * 16;
            uint32_t ah[2][4];
#pragma unroll
            for (int i = 0; i < 2; i++) {
                uint32_t off = (uint32_t)(((wm + i * 16 + lrow) * AP + kb + lcol) * 2);
                ldsm_x4(aA + off, ah[i]);
            }
#pragma unroll
            for (int p = 0; p < 4; p++) {
                uint32_t off = (uint32_t)(((wn + p * 16 + lrow) * AP + kb + lcol) * 2);
                uint32_t bh[4];
                ldsm_x4(aB + off, bh);
#pragma unroll
                for (int i = 0; i < 2; i++) {
                    mma16816h(acc[i][2 * p],     ah[i], bh[0], bh[2]);
                    mma16816h(acc[i][2 * p + 1], ah[i], bh[1], bh[3]);
                }
            }
        }
        __syncthreads();
    }

#pragma unroll
    for (int i = 0; i < 2; i++) {
#pragma unroll
        for (int half = 0; half < 2; half++) {
            int ml = wm + i * 16 + half * 8 + (lane >> 2);
            int s = s0 + ml;
#pragma unroll
            for (int n = 0; n < 8; n++) {
                int nn = n0 + wn + (lane & 3) * 2 + n * 8;
                if (nn < 200) {
                    float2 v = make_float2(
                        tanhapx(acc[i][n][half * 2] + __ldg(&b1[nn])),
                        tanhapx(acc[i][n][half * 2 + 1] + __ldg(&b1[nn + 1])));
                    *(float2*)&g_hid[(size_t)s * 200 + nn] = v;
                }
            }
        }
    }
}

// ---------------- MLP2 + softmax: one warp per sample ----------------
__global__ __launch_bounds__(128) void k_mlp2(
    const float* __restrict__ w2, const float* __restrict__ b2, float* __restrict__ out)
{
    __shared__ float w2s[800];
    __shared__ float b2s[4];
    const int tid = threadIdx.x;
    for (int i = tid; i < 800; i += 128) w2s[i] = w2[i];
    if (tid < 4) b2s[tid] = b2[tid];
    __syncthreads();
    const int warp = tid >> 5, lane = tid & 31;
    const int s = blockIdx.x * 4 + warp;
    const float* hr = g_hid + (size_t)s * 200;
    float a0 = 0.f, a1 = 0.f, a2 = 0.f, a3 = 0.f;
    for (int k = lane; k < 200; k += 32) {
        float h = hr[k];
        a0 += h * w2s[k];
        a1 += h * w2s[200 + k];
        a2 += h * w2s[400 + k];
        a3 += h * w2s[600 + k];
    }
#pragma unroll
    for (int o = 16; o > 0; o >>= 1) {
        a0 += __shfl_down_sync(0xffffffffu, a0, o);
        a1 += __shfl_down_sync(0xffffffffu, a1, o);
        a2 += __shfl_down_sync(0xffffffffu, a2, o);
        a3 += __shfl_down_sync(0xffffffffu, a3, o);
    }
    if (lane == 0) {
        float l0 = a0 + b2s[0], l1 = a1 + b2s[1], l2 = a2 + b2s[2], l3 = a3 + b2s[3];
        float m = fmaxf(fmaxf(l0, l1), fmaxf(l2, l3));
        float e0 = expf(l0 - m), e1 = expf(l1 - m), e2 = expf(l2 - m), e3 = expf(l3 - m);
        float inv = 1.f / (e0 + e1 + e2 + e3);
        float4 r = make_float4(e0 * inv, e1 * inv, e2 * inv, e3 * inv);
        *(float4*)&out[(size_t)s * 4] = r;
    }
}

extern "C" void kernel_launch(void* const* d_in, const int* in_sizes, int n_in,
                              void* d_out, int out_size)
{
    const int* tokens = (const int*)d_in[0];
    const int* paths = (const int*)d_in[1];
    const float* emb = (const float*)d_in[2];
    const float* wih0f = (const float*)d_in[3];
    const float* whh0f = (const float*)d_in[4];
    const float* bih0f = (const float*)d_in[5];
    const float* bhh0f = (const float*)d_in[6];
    const float* wih0b = (const float*)d_in[7];
    const float* whh0b = (const float*)d_in[8];
    const float* bih0b = (const float*)d_in[9];
    const float* bhh0b = (const float*)d_in[10];
    const float* wih1f = (const float*)d_in[11];
    const float* whh1f = (const float*)d_in[12];
    const float* bih1f = (const float*)d_in[13];
    const float* bhh1f = (const float*)d_in[14];
    const float* wih1b = (const float*)d_in[15];
    const float* whh1b = (const float*)d_in[16];
    const float* bih1b = (const float*)d_in[17];
    const float* bhh1b = (const float*)d_in[18];
    const float* w1 = (const float*)d_in[19];
    const float* b1 = (const float*)d_in[20];
    const float* w2 = (const float*)d_in[21];
    const float* b2 = (const float*)d_in[22];
    float* out = (float*)d_out;

    cudaFuncSetAttribute(k_recur_mma, cudaFuncAttributeMaxDynamicSharedMemorySize, RSMEM3);

    k_embsplit<<<TT, 256>>>(tokens, emb);                               // launch 1
    dim3 gw((896 * KP1 + 255) / 256, 9);
    k_prepw<<<gw, 256>>>(wih0f, wih0b, wih1f, wih1b,
                         whh0f, whh0b, whh1f, whh1b, w1);               // launch 2

    dim3 gg(7, TT, 2);
    k_gemm_mma<<<gg, 256>>>(0, bih0f, bhh0f, bih0b, bhh0b);             // launch 3
    k_recur_mma<<<32, 512, RSMEM3>>>(0);                                // launch 4 (profiled)
    k_gemm_mma<<<gg, 256>>>(1, bih1f, bhh1f, bih1b, bhh1b);             // launch 5
    k_recur_mma<<<32, 512, RSMEM3>>>(1);                                // launch 6

    dim3 g4(NSAMP / 128, 2);
    k_gather_mma<<<g4, 256>>>(paths, b1);                               // launch 7
    k_mlp2<<<NSAMP / 4, 128>>>(w2, b2, out);                            // launch 8
}